// round 1
// baseline (speedup 1.0000x reference)
#include <cuda_runtime.h>
#include <cuda_bf16.h>
#include <math.h>

// ---------------- problem constants ----------------
#define BB 8
#define LL 1024
#define CC 1024
#define HH 16
#define DKK 64
#define NTOK (BB*LL)            // 8192
#define EE 16
#define HIDD 64
#define CAPP 256                // int(0.5 * 8192 / 16)
#define NCE ((size_t)NTOK * CC) // 8388608 elements

// ---------------- scratch (static device globals; no allocs allowed) ----------------
__device__ float g_Q [NTOK * CC];   // Q proj; reused as att output after attention
__device__ float g_K [NTOK * CC];
__device__ float g_V [NTOK * CC];
__device__ float g_Z [NTOK * CC];   // attention context (pre-WO)
__device__ float g_zn[NTOK * CC];   // layernorm output
__device__ float g_eb[EE * CAPP * CC];   // expert input buffer
__device__ float g_h [EE * CAPP * HIDD]; // expert hidden
__device__ float g_y [EE * CAPP * CC];   // expert output
__device__ int   g_route[NTOK];
__device__ int   g_pos  [NTOK];

// ---------------- generic SGEMM: Y[M,N] = X[M,K] @ W[N,K]^T + bias[N] ----------------
// 128x128 tile, BK=8, 256 threads, 8x8 per thread.
__global__ void __launch_bounds__(256)
sgemm_xt(const float* __restrict__ X, const float* __restrict__ W,
         const float* __restrict__ bias, float* __restrict__ Y,
         int M, int N, int K)
{
    __shared__ float As[8][128];
    __shared__ float Bs[8][128];
    int tid = threadIdx.x;
    int bn = blockIdx.x * 128;
    int bm = blockIdx.y * 128;
    int tx = tid & 15, ty = tid >> 4;
    int lr = tid >> 1;
    int lc = (tid & 1) * 4;
    const float* Xp = X + (size_t)(bm + lr) * K + lc;
    const float* Wp = W + (size_t)(bn + lr) * K + lc;
    float acc[8][8] = {};
    for (int k0 = 0; k0 < K; k0 += 8) {
        float4 a  = *(const float4*)(Xp + k0);
        float4 bv = *(const float4*)(Wp + k0);
        __syncthreads();
        As[lc+0][lr]=a.x;  As[lc+1][lr]=a.y;  As[lc+2][lr]=a.z;  As[lc+3][lr]=a.w;
        Bs[lc+0][lr]=bv.x; Bs[lc+1][lr]=bv.y; Bs[lc+2][lr]=bv.z; Bs[lc+3][lr]=bv.w;
        __syncthreads();
        #pragma unroll
        for (int kk = 0; kk < 8; kk++) {
            float av[8], bw[8];
            *(float4*)&av[0] = *(float4*)&As[kk][ty*8];
            *(float4*)&av[4] = *(float4*)&As[kk][ty*8+4];
            *(float4*)&bw[0] = *(float4*)&Bs[kk][tx*8];
            *(float4*)&bw[4] = *(float4*)&Bs[kk][tx*8+4];
            #pragma unroll
            for (int i = 0; i < 8; i++)
                #pragma unroll
                for (int j = 0; j < 8; j++)
                    acc[i][j] += av[i] * bw[j];
        }
    }
    #pragma unroll
    for (int i = 0; i < 8; i++) {
        size_t row = (size_t)(bm + ty*8 + i);
        float* yp = Y + row * N + bn + tx*8;
        #pragma unroll
        for (int j4 = 0; j4 < 2; j4++) {
            const float* bp = bias + bn + tx*8 + j4*4;
            float4 o;
            o.x = acc[i][j4*4+0] + bp[0];
            o.y = acc[i][j4*4+1] + bp[1];
            o.z = acc[i][j4*4+2] + bp[2];
            o.w = acc[i][j4*4+3] + bp[3];
            *(float4*)(yp + j4*4) = o;
        }
    }
}

// ---------------- flash attention (fp32, non-causal, no mask) ----------------
// grid (L/64, B*H); 256 threads; Q-tile 64, K-tile 32.
__global__ void __launch_bounds__(256)
attn_kernel(const float* __restrict__ Q, const float* __restrict__ K,
            const float* __restrict__ V, float* __restrict__ Z)
{
    __shared__ float Qs[64][68];
    __shared__ float Ks[32][68];
    __shared__ float Vs[32][68];
    __shared__ float Ss[64][33];
    int tid = threadIdx.x;
    int tx = tid & 15, ty = tid >> 4;
    int bh = blockIdx.y;
    int b = bh >> 4, hh = bh & 15;
    int q0 = blockIdx.x * 64;
    size_t baseq = ((size_t)(b*LL + q0)) * CC + hh*DKK;

    for (int i = tid; i < 64*16; i += 256) {
        int r = i >> 4, c4 = (i & 15) * 4;
        *(float4*)&Qs[r][c4] = *(const float4*)(Q + baseq + (size_t)r*CC + c4);
    }

    float acc[4][4] = {};
    float m_i[4], l_i[4];
    #pragma unroll
    for (int i = 0; i < 4; i++) { m_i[i] = -1e30f; l_i[i] = 0.f; }

    for (int kt = 0; kt < LL/32; kt++) {
        __syncthreads();
        size_t basek = ((size_t)(b*LL + kt*32)) * CC + hh*DKK;
        for (int i = tid; i < 32*16; i += 256) {
            int r = i >> 4, c4 = (i & 15) * 4;
            *(float4*)&Ks[r][c4] = *(const float4*)(K + basek + (size_t)r*CC + c4);
            *(float4*)&Vs[r][c4] = *(const float4*)(V + basek + (size_t)r*CC + c4);
        }
        __syncthreads();

        float s[4][2] = {};
        #pragma unroll
        for (int d4 = 0; d4 < 16; d4++) {
            float4 qv[4], kv[2];
            #pragma unroll
            for (int i = 0; i < 4; i++) qv[i] = *(float4*)&Qs[ty*4+i][d4*4];
            #pragma unroll
            for (int j = 0; j < 2; j++) kv[j] = *(float4*)&Ks[tx + 16*j][d4*4];
            #pragma unroll
            for (int i = 0; i < 4; i++)
                #pragma unroll
                for (int j = 0; j < 2; j++)
                    s[i][j] += qv[i].x*kv[j].x + qv[i].y*kv[j].y
                             + qv[i].z*kv[j].z + qv[i].w*kv[j].w;
        }

        #pragma unroll
        for (int i = 0; i < 4; i++) {
            float s0 = s[i][0] * 0.125f;
            float s1 = s[i][1] * 0.125f;
            float mt = fmaxf(s0, s1);
            #pragma unroll
            for (int o = 8; o; o >>= 1)
                mt = fmaxf(mt, __shfl_xor_sync(0xffffffffu, mt, o, 16));
            float mn = fmaxf(m_i[i], mt);
            float al = __expf(m_i[i] - mn);
            float p0 = __expf(s0 - mn);
            float p1 = __expf(s1 - mn);
            float rs = p0 + p1;
            #pragma unroll
            for (int o = 8; o; o >>= 1)
                rs += __shfl_xor_sync(0xffffffffu, rs, o, 16);
            l_i[i] = l_i[i] * al + rs;
            m_i[i] = mn;
            Ss[ty*4+i][tx]      = p0;
            Ss[ty*4+i][tx + 16] = p1;
            acc[i][0]*=al; acc[i][1]*=al; acc[i][2]*=al; acc[i][3]*=al;
        }
        __syncthreads();

        #pragma unroll 8
        for (int kk = 0; kk < 32; kk++) {
            float4 vv = *(float4*)&Vs[kk][tx*4];
            #pragma unroll
            for (int i = 0; i < 4; i++) {
                float p = Ss[ty*4+i][kk];
                acc[i][0] += p*vv.x; acc[i][1] += p*vv.y;
                acc[i][2] += p*vv.z; acc[i][3] += p*vv.w;
            }
        }
    }

    #pragma unroll
    for (int i = 0; i < 4; i++) {
        float inv = 1.f / l_i[i];
        float4 o;
        o.x = acc[i][0]*inv; o.y = acc[i][1]*inv;
        o.z = acc[i][2]*inv; o.w = acc[i][3]*inv;
        *(float4*)(Z + baseq + (size_t)(ty*4+i)*CC + tx*4) = o;
    }
}

// ---------------- block reduce helper ----------------
__device__ __forceinline__ float blockReduceSum256(float v, float* red /*>=8*/)
{
    int lane = threadIdx.x & 31, warp = threadIdx.x >> 5;
    #pragma unroll
    for (int o = 16; o; o >>= 1) v += __shfl_xor_sync(0xffffffffu, v, o);
    if (lane == 0) red[warp] = v;
    __syncthreads();
    if (warp == 0) {
        v = (lane < 8) ? red[lane] : 0.f;
        #pragma unroll
        for (int o = 4; o; o >>= 1) v += __shfl_xor_sync(0xffffffffu, v, o);
        if (lane == 0) red[0] = v;
    }
    __syncthreads();
    float r = red[0];
    __syncthreads();
    return r;
}

// ---------------- residual add + LayerNorm ----------------
__global__ void __launch_bounds__(256)
add_ln_kernel(const float* __restrict__ qx, const float* __restrict__ att,
              const float* __restrict__ w, const float* __restrict__ bb,
              float* __restrict__ zn)
{
    __shared__ float red[8];
    int row = blockIdx.x, tid = threadIdx.x;
    const float4* xq = (const float4*)(qx  + (size_t)row * CC);
    const float4* aq = (const float4*)(att + (size_t)row * CC);
    float4 x = xq[tid], a = aq[tid];
    float4 v; v.x = x.x + a.x; v.y = x.y + a.y; v.z = x.z + a.z; v.w = x.w + a.w;
    float mean = blockReduceSum256(v.x + v.y + v.z + v.w, red) * (1.f/1024.f);
    float dx = v.x - mean, dy = v.y - mean, dz = v.z - mean, dw = v.w - mean;
    float var = blockReduceSum256(dx*dx + dy*dy + dz*dz + dw*dw, red) * (1.f/1024.f);
    float rs = rsqrtf(var + 1e-5f);
    float4 wv = ((const float4*)w)[tid];
    float4 bv = ((const float4*)bb)[tid];
    float4 o;
    o.x = dx*rs*wv.x + bv.x; o.y = dy*rs*wv.y + bv.y;
    o.z = dz*rs*wv.z + bv.z; o.w = dw*rs*wv.w + bv.w;
    ((float4*)(zn + (size_t)row * CC))[tid] = o;
}

// ---------------- router: argmax of logits (softmax scale == 1 in fwd) ----------------
__global__ void __launch_bounds__(128)
router_kernel(const float* __restrict__ zn, const float* __restrict__ Wsw,
              const float* __restrict__ bsw, int* __restrict__ route)
{
    int tok = blockIdx.x, tid = threadIdx.x;
    int lane = tid & 31, warp = tid >> 5;
    float part[EE] = {};
    for (int c = tid; c < CC; c += 128) {
        float xv = zn[(size_t)tok * CC + c];
        #pragma unroll
        for (int e = 0; e < EE; e++) part[e] += xv * Wsw[e*CC + c];
    }
    __shared__ float wsum[4][EE];
    #pragma unroll
    for (int e = 0; e < EE; e++) {
        float v = part[e];
        #pragma unroll
        for (int o = 16; o; o >>= 1) v += __shfl_xor_sync(0xffffffffu, v, o);
        if (lane == 0) wsum[warp][e] = v;
    }
    __syncthreads();
    if (tid == 0) {
        float best = -1e30f; int bi = 0;
        #pragma unroll
        for (int e = 0; e < EE; e++) {
            float lg = wsum[0][e] + wsum[1][e] + wsum[2][e] + wsum[3][e] + bsw[e];
            if (lg > best) { best = lg; bi = e; }   // strict > = first-max (jax argmax)
        }
        route[tok] = bi;
    }
}

// ---------------- deterministic per-expert prefix positions (token-index order) -----
__global__ void __launch_bounds__(256)
scanpos_kernel(const int* __restrict__ route, int* __restrict__ pos)
{
    int e = blockIdx.x;
    int tid = threadIdx.x;
    int lane = tid & 31, warp = tid >> 5;
    __shared__ int wtot[8];
    __shared__ int running;
    if (tid == 0) running = 0;
    __syncthreads();
    for (int base = 0; base < NTOK; base += 256) {
        int tok = base + tid;
        int flag = (route[tok] == e);
        unsigned m = __ballot_sync(0xffffffffu, flag);
        int rank = __popc(m & ((1u << lane) - 1u));
        if (lane == 31) wtot[warp] = __popc(m);
        __syncthreads();
        int prefix = 0;
        for (int w = 0; w < warp; w++) prefix += wtot[w];
        if (flag) pos[tok] = running + prefix + rank;
        __syncthreads();
        if (tid == 0) {
            int t = 0;
            for (int w = 0; w < 8; w++) t += wtot[w];
            running += t;
        }
        __syncthreads();
    }
}

// ---------------- gather kept tokens into expert buffers ----------------
__global__ void __launch_bounds__(256)
gather_kernel(const float* __restrict__ zn, const int* __restrict__ route,
              const int* __restrict__ pos, float* __restrict__ eb)
{
    int tok = blockIdx.x;
    int p = pos[tok];
    if (p >= CAPP) return;
    size_t slot = (size_t)route[tok] * CAPP + p;
    ((float4*)(eb + slot * CC))[threadIdx.x] =
        ((const float4*)(zn + (size_t)tok * CC))[threadIdx.x];
}

// ---------------- expert FFN layer 1: h = relu(eb @ W1[e] + b1[e]) ----------------
// 4 rows per block; grid = E * CAP/4 = 1024
__global__ void __launch_bounds__(256)
ffn1_kernel(const float* __restrict__ eb, const float* __restrict__ W1,
            const float* __restrict__ b1, float* __restrict__ h)
{
    int blk = blockIdx.x;
    int e  = blk >> 6;
    int r0 = (blk & 63) * 4;
    __shared__ float xs[4][CC];
    __shared__ float red[4][4][HIDD];
    int tid = threadIdx.x;
    const float4* src = (const float4*)(eb + ((size_t)e*CAPP + r0) * CC);
    for (int i = tid; i < 4 * (CC/4); i += 256)
        ((float4*)xs)[i] = src[i];
    __syncthreads();
    int kp = tid >> 6;
    int n  = tid & 63;
    float acc[4] = {};
    const float* w = W1 + (size_t)e * CC * HIDD + n;
    #pragma unroll 4
    for (int k = kp; k < CC; k += 4) {
        float wv = w[(size_t)k * HIDD];
        #pragma unroll
        for (int r = 0; r < 4; r++) acc[r] += xs[r][k] * wv;
    }
    #pragma unroll
    for (int r = 0; r < 4; r++) red[kp][r][n] = acc[r];
    __syncthreads();
    {
        int r = tid >> 6, n2 = tid & 63;
        float s = red[0][r][n2] + red[1][r][n2] + red[2][r][n2] + red[3][r][n2]
                + b1[e*HIDD + n2];
        h[((size_t)e*CAPP + r0 + r) * HIDD + n2] = fmaxf(s, 0.f);
    }
}

// ---------------- expert FFN layer 2: y = h @ W2[e] + b2[e] ----------------
// 4 rows per block; grid = 1024
__global__ void __launch_bounds__(256)
ffn2_kernel(const float* __restrict__ h, const float* __restrict__ W2,
            const float* __restrict__ b2, float* __restrict__ y)
{
    int blk = blockIdx.x;
    int e  = blk >> 6;
    int r0 = (blk & 63) * 4;
    __shared__ float hs[4][HIDD];
    int tid = threadIdx.x;
    hs[tid >> 6][tid & 63] = h[((size_t)e*CAPP + r0 + (tid >> 6)) * HIDD + (tid & 63)];
    __syncthreads();
    int c = tid * 4;
    float4 acc[4];
    #pragma unroll
    for (int r = 0; r < 4; r++) { acc[r].x=0.f; acc[r].y=0.f; acc[r].z=0.f; acc[r].w=0.f; }
    const float* w = W2 + (size_t)e * HIDD * CC + c;
    #pragma unroll 8
    for (int k = 0; k < HIDD; k++) {
        float4 wv = *(const float4*)(w + (size_t)k * CC);
        #pragma unroll
        for (int r = 0; r < 4; r++) {
            float hv = hs[r][k];
            acc[r].x += hv*wv.x; acc[r].y += hv*wv.y;
            acc[r].z += hv*wv.z; acc[r].w += hv*wv.w;
        }
    }
    float4 bb = *(const float4*)(b2 + (size_t)e * CC + c);
    #pragma unroll
    for (int r = 0; r < 4; r++) {
        float4 o;
        o.x = acc[r].x + bb.x; o.y = acc[r].y + bb.y;
        o.z = acc[r].z + bb.z; o.w = acc[r].w + bb.w;
        *(float4*)(y + ((size_t)e*CAPP + r0 + r) * CC + c) = o;
    }
}

// ---------------- final: out = zn + (kept ? y[slot] : zn) ----------------
__global__ void __launch_bounds__(256)
finalize_kernel(const float* __restrict__ zn, const float* __restrict__ y,
                const int* __restrict__ route, const int* __restrict__ pos,
                float* __restrict__ out)
{
    int tok = blockIdx.x, tid = threadIdx.x;
    int p = pos[tok];
    float4 z = ((const float4*)(zn + (size_t)tok * CC))[tid];
    float4 o;
    if (p < CAPP) {
        float4 yv = ((const float4*)(y + ((size_t)route[tok]*CAPP + p) * CC))[tid];
        o.x = z.x + yv.x; o.y = z.y + yv.y; o.z = z.z + yv.z; o.w = z.w + yv.w;
    } else {
        o.x = 2.f*z.x; o.y = 2.f*z.y; o.z = 2.f*z.z; o.w = 2.f*z.w;
    }
    ((float4*)(out + (size_t)tok * CC))[tid] = o;
}

__global__ void fill_ones_kernel(float* __restrict__ p, int n)
{
    int i = blockIdx.x * 256 + threadIdx.x;
    if (i < n) p[i] = 1.0f;
}

// ---------------- launch ----------------
extern "C" void kernel_launch(void* const* d_in, const int* in_sizes, int n_in,
                              void* d_out, int out_size)
{
    const float* qx  = (const float*)d_in[0];
    const float* kx  = (const float*)d_in[1];
    const float* vx  = (const float*)d_in[2];
    // d_in[3] = maskPAD (unused by the math; always all-true)
    const float* WQ  = (const float*)d_in[4];
    const float* bQ  = (const float*)d_in[5];
    const float* WK  = (const float*)d_in[6];
    const float* bK  = (const float*)d_in[7];
    const float* WV  = (const float*)d_in[8];
    const float* bV  = (const float*)d_in[9];
    const float* WO  = (const float*)d_in[10];
    const float* bO  = (const float*)d_in[11];
    const float* ln1w= (const float*)d_in[12];
    const float* ln1b= (const float*)d_in[13];
    const float* Wsw = (const float*)d_in[14];
    const float* bsw = (const float*)d_in[15];
    const float* W1  = (const float*)d_in[16];
    const float* b1  = (const float*)d_in[17];
    const float* W2  = (const float*)d_in[18];
    const float* b2  = (const float*)d_in[19];
    float* out = (float*)d_out;

    float *pQ, *pK, *pV, *pZ, *pzn, *peb, *ph, *py;
    int *proute, *ppos;
    cudaGetSymbolAddress((void**)&pQ,  g_Q);
    cudaGetSymbolAddress((void**)&pK,  g_K);
    cudaGetSymbolAddress((void**)&pV,  g_V);
    cudaGetSymbolAddress((void**)&pZ,  g_Z);
    cudaGetSymbolAddress((void**)&pzn, g_zn);
    cudaGetSymbolAddress((void**)&peb, g_eb);
    cudaGetSymbolAddress((void**)&ph,  g_h);
    cudaGetSymbolAddress((void**)&py,  g_y);
    cudaGetSymbolAddress((void**)&proute, g_route);
    cudaGetSymbolAddress((void**)&ppos,   g_pos);

    dim3 gemmGrid(CC/128, NTOK/128);   // (8, 64)
    sgemm_xt<<<gemmGrid, 256>>>(qx, WQ, bQ, pQ, NTOK, CC, CC);
    sgemm_xt<<<gemmGrid, 256>>>(kx, WK, bK, pK, NTOK, CC, CC);
    sgemm_xt<<<gemmGrid, 256>>>(vx, WV, bV, pV, NTOK, CC, CC);

    attn_kernel<<<dim3(LL/64, BB*HH), 256>>>(pQ, pK, pV, pZ);

    // WO projection; reuse g_Q as att buffer
    sgemm_xt<<<gemmGrid, 256>>>(pZ, WO, bO, pQ, NTOK, CC, CC);

    add_ln_kernel<<<NTOK, 256>>>(qx, pQ, ln1w, ln1b, pzn);
    router_kernel<<<NTOK, 128>>>(pzn, Wsw, bsw, proute);
    scanpos_kernel<<<EE, 256>>>(proute, ppos);
    gather_kernel<<<NTOK, 256>>>(pzn, proute, ppos, peb);
    ffn1_kernel<<<EE * (CAPP/4), 256>>>(peb, W1, b1, ph);
    ffn2_kernel<<<EE * (CAPP/4), 256>>>(ph, W2, b2, py);
    finalize_kernel<<<NTOK, 256>>>(pzn, py, proute, ppos, out);

    // tuple output: (out, kx, vx, maskPAD) flattened — detect by out_size
    long long os = (long long)out_size;
    if (os >= (long long)(2 * NCE)) {
        cudaMemcpyAsync(out + NCE, kx, NCE * sizeof(float),
                        cudaMemcpyDeviceToDevice, 0);
    }
    if (os >= (long long)(3 * NCE)) {
        cudaMemcpyAsync(out + 2 * NCE, vx, NCE * sizeof(float),
                        cudaMemcpyDeviceToDevice, 0);
    }
    long long rem = os - (long long)(3 * NCE);
    if (rem > 0) {
        fill_ones_kernel<<<(int)((rem + 255) / 256), 256>>>(out + 3 * NCE, (int)rem);
    }
}

// round 2
// speedup vs baseline: 1.0194x; 1.0194x over previous
#include <cuda_runtime.h>
#include <cuda_bf16.h>
#include <math.h>

// ---------------- problem constants ----------------
#define BB 8
#define LL 1024
#define CC 1024
#define HH 16
#define DKK 64
#define NTOK (BB*LL)            // 8192
#define EE 16
#define HIDD 64
#define CAPP 256                // int(0.5 * 8192 / 16)
#define NCE ((size_t)NTOK * CC) // 8388608 elements

typedef unsigned long long ull;

// ---------------- f32x2 packed math helpers (Blackwell) ----------------
__device__ __forceinline__ ull pk2(float x, float y) {
    ull r; asm("mov.b64 %0, {%1,%2};" : "=l"(r) : "f"(x), "f"(y)); return r;
}
__device__ __forceinline__ void upk2(ull v, float& x, float& y) {
    asm("mov.b64 {%0,%1}, %2;" : "=f"(x), "=f"(y) : "l"(v));
}
#define FFMA2(d, a, b) asm("fma.rn.f32x2 %0, %1, %2, %0;" : "+l"(d) : "l"(a), "l"(b))
#define FMUL2(d, a, b) asm("mul.rn.f32x2 %0, %1, %2;" : "=l"(d) : "l"(a), "l"(b))

// ---------------- scratch (static device globals; no allocs allowed) ----------------
__device__ float g_Q [NTOK * CC];
__device__ float g_K [NTOK * CC];
__device__ float g_V [NTOK * CC];
__device__ float g_Z [NTOK * CC];
__device__ float g_zn[NTOK * CC];
__device__ float g_eb[EE * CAPP * CC];
__device__ float g_h [EE * CAPP * HIDD];
__device__ float g_y [EE * CAPP * CC];
__device__ int   g_route[NTOK];
__device__ int   g_pos  [NTOK];

// ---------------- SGEMM: Y[M,N] = X[M,K] @ W[N,K]^T + bias[N] ----------------
// 128x128 tile, BK=8, 256 threads, 8x8 per thread, double-buffered smem,
// f32x2 packed FMA accumulators.
__global__ void __launch_bounds__(256)
sgemm_xt(const float* __restrict__ X, const float* __restrict__ W,
         const float* __restrict__ bias, float* __restrict__ Y,
         int M, int N, int K)
{
    __shared__ float As[2][8][128];
    __shared__ float Bs[2][8][128];
    int tid = threadIdx.x;
    int bn = blockIdx.x * 128;
    int bm = blockIdx.y * 128;
    int tx = tid & 15, ty = tid >> 4;
    int lr = tid >> 1;
    int lc = (tid & 1) * 4;
    const float* Xp = X + (size_t)(bm + lr) * K + lc;
    const float* Wp = W + (size_t)(bn + lr) * K + lc;

    // prologue: tile 0
    float4 a  = *(const float4*)Xp;
    float4 bv = *(const float4*)Wp;
    As[0][lc+0][lr]=a.x;  As[0][lc+1][lr]=a.y;  As[0][lc+2][lr]=a.z;  As[0][lc+3][lr]=a.w;
    Bs[0][lc+0][lr]=bv.x; Bs[0][lc+1][lr]=bv.y; Bs[0][lc+2][lr]=bv.z; Bs[0][lc+3][lr]=bv.w;
    __syncthreads();

    ull acc[8][4];
    #pragma unroll
    for (int i = 0; i < 8; i++)
        #pragma unroll
        for (int j = 0; j < 4; j++) acc[i][j] = 0ull;

    int nIter = K >> 3;
    for (int t = 0; t < nIter; t++) {
        int buf = t & 1;
        if (t + 1 < nIter) {
            a  = *(const float4*)(Xp + (t+1)*8);
            bv = *(const float4*)(Wp + (t+1)*8);
        }
        #pragma unroll
        for (int kk = 0; kk < 8; kk++) {
            float4 av0 = *(float4*)&As[buf][kk][ty*8];
            float4 av1 = *(float4*)&As[buf][kk][ty*8+4];
            float4 bw0 = *(float4*)&Bs[buf][kk][tx*8];
            float4 bw1 = *(float4*)&Bs[buf][kk][tx*8+4];
            ull bp[4];
            bp[0] = *reinterpret_cast<ull*>(&bw0.x);
            bp[1] = *reinterpret_cast<ull*>(&bw0.z);
            bp[2] = *reinterpret_cast<ull*>(&bw1.x);
            bp[3] = *reinterpret_cast<ull*>(&bw1.z);
            float avf[8];
            avf[0]=av0.x; avf[1]=av0.y; avf[2]=av0.z; avf[3]=av0.w;
            avf[4]=av1.x; avf[5]=av1.y; avf[6]=av1.z; avf[7]=av1.w;
            #pragma unroll
            for (int i = 0; i < 8; i++) {
                ull ap = pk2(avf[i], avf[i]);
                FFMA2(acc[i][0], ap, bp[0]);
                FFMA2(acc[i][1], ap, bp[1]);
                FFMA2(acc[i][2], ap, bp[2]);
                FFMA2(acc[i][3], ap, bp[3]);
            }
        }
        if (t + 1 < nIter) {
            int nb = buf ^ 1;
            As[nb][lc+0][lr]=a.x;  As[nb][lc+1][lr]=a.y;  As[nb][lc+2][lr]=a.z;  As[nb][lc+3][lr]=a.w;
            Bs[nb][lc+0][lr]=bv.x; Bs[nb][lc+1][lr]=bv.y; Bs[nb][lc+2][lr]=bv.z; Bs[nb][lc+3][lr]=bv.w;
        }
        __syncthreads();
    }

    #pragma unroll
    for (int i = 0; i < 8; i++) {
        size_t row = (size_t)(bm + ty*8 + i);
        float* yp = Y + row * N + bn + tx*8;
        const float* bp = bias + bn + tx*8;
        float4 o0, o1;
        upk2(acc[i][0], o0.x, o0.y);
        upk2(acc[i][1], o0.z, o0.w);
        upk2(acc[i][2], o1.x, o1.y);
        upk2(acc[i][3], o1.z, o1.w);
        o0.x += bp[0]; o0.y += bp[1]; o0.z += bp[2]; o0.w += bp[3];
        o1.x += bp[4]; o1.y += bp[5]; o1.z += bp[6]; o1.w += bp[7];
        *(float4*)(yp)     = o0;
        *(float4*)(yp + 4) = o1;
    }
}

// ---------------- flash attention (fp32, f32x2 inner math) ----------------
__global__ void __launch_bounds__(256)
attn_kernel(const float* __restrict__ Q, const float* __restrict__ K,
            const float* __restrict__ V, float* __restrict__ Z)
{
    __shared__ float Qs[64][68];
    __shared__ float Ks[32][68];
    __shared__ float Vs[32][68];
    __shared__ float Ss[64][33];
    int tid = threadIdx.x;
    int tx = tid & 15, ty = tid >> 4;
    int bh = blockIdx.y;
    int b = bh >> 4, hh = bh & 15;
    int q0 = blockIdx.x * 64;
    size_t baseq = ((size_t)(b*LL + q0)) * CC + hh*DKK;

    for (int i = tid; i < 64*16; i += 256) {
        int r = i >> 4, c4 = (i & 15) * 4;
        *(float4*)&Qs[r][c4] = *(const float4*)(Q + baseq + (size_t)r*CC + c4);
    }

    ull accp[4][2];
    #pragma unroll
    for (int i = 0; i < 4; i++) { accp[i][0] = 0ull; accp[i][1] = 0ull; }
    float m_i[4], l_i[4];
    #pragma unroll
    for (int i = 0; i < 4; i++) { m_i[i] = -1e30f; l_i[i] = 0.f; }

    for (int kt = 0; kt < LL/32; kt++) {
        __syncthreads();
        size_t basek = ((size_t)(b*LL + kt*32)) * CC + hh*DKK;
        for (int i = tid; i < 32*16; i += 256) {
            int r = i >> 4, c4 = (i & 15) * 4;
            *(float4*)&Ks[r][c4] = *(const float4*)(K + basek + (size_t)r*CC + c4);
            *(float4*)&Vs[r][c4] = *(const float4*)(V + basek + (size_t)r*CC + c4);
        }
        __syncthreads();

        // QK^T: pairs along d (reduction) -- no packs needed
        ull s2[4][2];
        #pragma unroll
        for (int i = 0; i < 4; i++) { s2[i][0] = 0ull; s2[i][1] = 0ull; }
        #pragma unroll
        for (int d4 = 0; d4 < 16; d4++) {
            float4 qv[4], kv[2];
            #pragma unroll
            for (int i = 0; i < 4; i++) qv[i] = *(float4*)&Qs[ty*4+i][d4*4];
            #pragma unroll
            for (int j = 0; j < 2; j++) kv[j] = *(float4*)&Ks[tx + 16*j][d4*4];
            ull kp[2][2];
            kp[0][0] = *reinterpret_cast<ull*>(&kv[0].x);
            kp[0][1] = *reinterpret_cast<ull*>(&kv[0].z);
            kp[1][0] = *reinterpret_cast<ull*>(&kv[1].x);
            kp[1][1] = *reinterpret_cast<ull*>(&kv[1].z);
            #pragma unroll
            for (int i = 0; i < 4; i++) {
                ull qp0 = *reinterpret_cast<ull*>(&qv[i].x);
                ull qp1 = *reinterpret_cast<ull*>(&qv[i].z);
                FFMA2(s2[i][0], qp0, kp[0][0]);
                FFMA2(s2[i][0], qp1, kp[0][1]);
                FFMA2(s2[i][1], qp0, kp[1][0]);
                FFMA2(s2[i][1], qp1, kp[1][1]);
            }
        }

        #pragma unroll
        for (int i = 0; i < 4; i++) {
            float a0, a1, b0, b1;
            upk2(s2[i][0], a0, a1);
            upk2(s2[i][1], b0, b1);
            float s0 = (a0 + a1) * 0.125f;
            float s1 = (b0 + b1) * 0.125f;
            float mt = fmaxf(s0, s1);
            #pragma unroll
            for (int o = 8; o; o >>= 1)
                mt = fmaxf(mt, __shfl_xor_sync(0xffffffffu, mt, o, 16));
            float mn = fmaxf(m_i[i], mt);
            float al = __expf(m_i[i] - mn);
            float p0 = __expf(s0 - mn);
            float p1 = __expf(s1 - mn);
            float rs = p0 + p1;
            #pragma unroll
            for (int o = 8; o; o >>= 1)
                rs += __shfl_xor_sync(0xffffffffu, rs, o, 16);
            l_i[i] = l_i[i] * al + rs;
            m_i[i] = mn;
            Ss[ty*4+i][tx]      = p0;
            Ss[ty*4+i][tx + 16] = p1;
            ull alp = pk2(al, al);
            FMUL2(accp[i][0], accp[i][0], alp);
            FMUL2(accp[i][1], accp[i][1], alp);
        }
        __syncthreads();

        #pragma unroll 8
        for (int kk = 0; kk < 32; kk++) {
            float4 vv = *(float4*)&Vs[kk][tx*4];
            ull vp0 = *reinterpret_cast<ull*>(&vv.x);
            ull vp1 = *reinterpret_cast<ull*>(&vv.z);
            #pragma unroll
            for (int i = 0; i < 4; i++) {
                float p = Ss[ty*4+i][kk];
                ull pp = pk2(p, p);
                FFMA2(accp[i][0], pp, vp0);
                FFMA2(accp[i][1], pp, vp1);
            }
        }
    }

    #pragma unroll
    for (int i = 0; i < 4; i++) {
        float inv = 1.f / l_i[i];
        float4 o;
        upk2(accp[i][0], o.x, o.y);
        upk2(accp[i][1], o.z, o.w);
        o.x *= inv; o.y *= inv; o.z *= inv; o.w *= inv;
        *(float4*)(Z + baseq + (size_t)(ty*4+i)*CC + tx*4) = o;
    }
}

// ---------------- block reduce helper ----------------
__device__ __forceinline__ float blockReduceSum256(float v, float* red)
{
    int lane = threadIdx.x & 31, warp = threadIdx.x >> 5;
    #pragma unroll
    for (int o = 16; o; o >>= 1) v += __shfl_xor_sync(0xffffffffu, v, o);
    if (lane == 0) red[warp] = v;
    __syncthreads();
    if (warp == 0) {
        v = (lane < 8) ? red[lane] : 0.f;
        #pragma unroll
        for (int o = 4; o; o >>= 1) v += __shfl_xor_sync(0xffffffffu, v, o);
        if (lane == 0) red[0] = v;
    }
    __syncthreads();
    float r = red[0];
    __syncthreads();
    return r;
}

// ---------------- residual add + LayerNorm ----------------
__global__ void __launch_bounds__(256)
add_ln_kernel(const float* __restrict__ qx, const float* __restrict__ att,
              const float* __restrict__ w, const float* __restrict__ bb,
              float* __restrict__ zn)
{
    __shared__ float red[8];
    int row = blockIdx.x, tid = threadIdx.x;
    const float4* xq = (const float4*)(qx  + (size_t)row * CC);
    const float4* aq = (const float4*)(att + (size_t)row * CC);
    float4 x = xq[tid], a = aq[tid];
    float4 v; v.x = x.x + a.x; v.y = x.y + a.y; v.z = x.z + a.z; v.w = x.w + a.w;
    float mean = blockReduceSum256(v.x + v.y + v.z + v.w, red) * (1.f/1024.f);
    float dx = v.x - mean, dy = v.y - mean, dz = v.z - mean, dw = v.w - mean;
    float var = blockReduceSum256(dx*dx + dy*dy + dz*dz + dw*dw, red) * (1.f/1024.f);
    float rs = rsqrtf(var + 1e-5f);
    float4 wv = ((const float4*)w)[tid];
    float4 bv = ((const float4*)bb)[tid];
    float4 o;
    o.x = dx*rs*wv.x + bv.x; o.y = dy*rs*wv.y + bv.y;
    o.z = dz*rs*wv.z + bv.z; o.w = dw*rs*wv.w + bv.w;
    ((float4*)(zn + (size_t)row * CC))[tid] = o;
}

// ---------------- router: argmax of logits ----------------
__global__ void __launch_bounds__(128)
router_kernel(const float* __restrict__ zn, const float* __restrict__ Wsw,
              const float* __restrict__ bsw, int* __restrict__ route)
{
    int tok = blockIdx.x, tid = threadIdx.x;
    int lane = tid & 31, warp = tid >> 5;
    float part[EE] = {};
    for (int c = tid; c < CC; c += 128) {
        float xv = zn[(size_t)tok * CC + c];
        #pragma unroll
        for (int e = 0; e < EE; e++) part[e] += xv * Wsw[e*CC + c];
    }
    __shared__ float wsum[4][EE];
    #pragma unroll
    for (int e = 0; e < EE; e++) {
        float v = part[e];
        #pragma unroll
        for (int o = 16; o; o >>= 1) v += __shfl_xor_sync(0xffffffffu, v, o);
        if (lane == 0) wsum[warp][e] = v;
    }
    __syncthreads();
    if (tid == 0) {
        float best = -1e30f; int bi = 0;
        #pragma unroll
        for (int e = 0; e < EE; e++) {
            float lg = wsum[0][e] + wsum[1][e] + wsum[2][e] + wsum[3][e] + bsw[e];
            if (lg > best) { best = lg; bi = e; }
        }
        route[tok] = bi;
    }
}

// ---------------- deterministic per-expert prefix positions ----------------
__global__ void __launch_bounds__(256)
scanpos_kernel(const int* __restrict__ route, int* __restrict__ pos)
{
    int e = blockIdx.x;
    int tid = threadIdx.x;
    int lane = tid & 31, warp = tid >> 5;
    __shared__ int wtot[8];
    __shared__ int running;
    if (tid == 0) running = 0;
    __syncthreads();
    for (int base = 0; base < NTOK; base += 256) {
        int tok = base + tid;
        int flag = (route[tok] == e);
        unsigned m = __ballot_sync(0xffffffffu, flag);
        int rank = __popc(m & ((1u << lane) - 1u));
        if (lane == 31) wtot[warp] = __popc(m);
        __syncthreads();
        int prefix = 0;
        for (int w = 0; w < warp; w++) prefix += wtot[w];
        if (flag) pos[tok] = running + prefix + rank;
        __syncthreads();
        if (tid == 0) {
            int t = 0;
            for (int w = 0; w < 8; w++) t += wtot[w];
            running += t;
        }
        __syncthreads();
    }
}

// ---------------- gather kept tokens into expert buffers ----------------
__global__ void __launch_bounds__(256)
gather_kernel(const float* __restrict__ zn, const int* __restrict__ route,
              const int* __restrict__ pos, float* __restrict__ eb)
{
    int tok = blockIdx.x;
    int p = pos[tok];
    if (p >= CAPP) return;
    size_t slot = (size_t)route[tok] * CAPP + p;
    ((float4*)(eb + slot * CC))[threadIdx.x] =
        ((const float4*)(zn + (size_t)tok * CC))[threadIdx.x];
}

// ---------------- expert FFN layer 1 ----------------
__global__ void __launch_bounds__(256)
ffn1_kernel(const float* __restrict__ eb, const float* __restrict__ W1,
            const float* __restrict__ b1, float* __restrict__ h)
{
    int blk = blockIdx.x;
    int e  = blk >> 6;
    int r0 = (blk & 63) * 4;
    __shared__ float xs[4][CC];
    __shared__ float red[4][4][HIDD];
    int tid = threadIdx.x;
    const float4* src = (const float4*)(eb + ((size_t)e*CAPP + r0) * CC);
    for (int i = tid; i < 4 * (CC/4); i += 256)
        ((float4*)xs)[i] = src[i];
    __syncthreads();
    int kp = tid >> 6;
    int n  = tid & 63;
    float acc[4] = {};
    const float* w = W1 + (size_t)e * CC * HIDD + n;
    #pragma unroll 4
    for (int k = kp; k < CC; k += 4) {
        float wv = w[(size_t)k * HIDD];
        #pragma unroll
        for (int r = 0; r < 4; r++) acc[r] += xs[r][k] * wv;
    }
    #pragma unroll
    for (int r = 0; r < 4; r++) red[kp][r][n] = acc[r];
    __syncthreads();
    {
        int r = tid >> 6, n2 = tid & 63;
        float s = red[0][r][n2] + red[1][r][n2] + red[2][r][n2] + red[3][r][n2]
                + b1[e*HIDD + n2];
        h[((size_t)e*CAPP + r0 + r) * HIDD + n2] = fmaxf(s, 0.f);
    }
}

// ---------------- expert FFN layer 2 ----------------
__global__ void __launch_bounds__(256)
ffn2_kernel(const float* __restrict__ h, const float* __restrict__ W2,
            const float* __restrict__ b2, float* __restrict__ y)
{
    int blk = blockIdx.x;
    int e  = blk >> 6;
    int r0 = (blk & 63) * 4;
    __shared__ float hs[4][HIDD];
    int tid = threadIdx.x;
    hs[tid >> 6][tid & 63] = h[((size_t)e*CAPP + r0 + (tid >> 6)) * HIDD + (tid & 63)];
    __syncthreads();
    int c = tid * 4;
    float4 acc[4];
    #pragma unroll
    for (int r = 0; r < 4; r++) { acc[r].x=0.f; acc[r].y=0.f; acc[r].z=0.f; acc[r].w=0.f; }
    const float* w = W2 + (size_t)e * HIDD * CC + c;
    #pragma unroll 8
    for (int k = 0; k < HIDD; k++) {
        float4 wv = *(const float4*)(w + (size_t)k * CC);
        #pragma unroll
        for (int r = 0; r < 4; r++) {
            float hv = hs[r][k];
            acc[r].x += hv*wv.x; acc[r].y += hv*wv.y;
            acc[r].z += hv*wv.z; acc[r].w += hv*wv.w;
        }
    }
    float4 bb = *(const float4*)(b2 + (size_t)e * CC + c);
    #pragma unroll
    for (int r = 0; r < 4; r++) {
        float4 o;
        o.x = acc[r].x + bb.x; o.y = acc[r].y + bb.y;
        o.z = acc[r].z + bb.z; o.w = acc[r].w + bb.w;
        *(float4*)(y + ((size_t)e*CAPP + r0 + r) * CC + c) = o;
    }
}

// ---------------- final: out = zn + (kept ? y[slot] : zn) ----------------
__global__ void __launch_bounds__(256)
finalize_kernel(const float* __restrict__ zn, const float* __restrict__ y,
                const int* __restrict__ route, const int* __restrict__ pos,
                float* __restrict__ out)
{
    int tok = blockIdx.x, tid = threadIdx.x;
    int p = pos[tok];
    float4 z = ((const float4*)(zn + (size_t)tok * CC))[tid];
    float4 o;
    if (p < CAPP) {
        float4 yv = ((const float4*)(y + ((size_t)route[tok]*CAPP + p) * CC))[tid];
        o.x = z.x + yv.x; o.y = z.y + yv.y; o.z = z.z + yv.z; o.w = z.w + yv.w;
    } else {
        o.x = 2.f*z.x; o.y = 2.f*z.y; o.z = 2.f*z.z; o.w = 2.f*z.w;
    }
    ((float4*)(out + (size_t)tok * CC))[tid] = o;
}

__global__ void fill_ones_kernel(float* __restrict__ p, int n)
{
    int i = blockIdx.x * 256 + threadIdx.x;
    if (i < n) p[i] = 1.0f;
}

// ---------------- launch ----------------
extern "C" void kernel_launch(void* const* d_in, const int* in_sizes, int n_in,
                              void* d_out, int out_size)
{
    const float* qx  = (const float*)d_in[0];
    const float* kx  = (const float*)d_in[1];
    const float* vx  = (const float*)d_in[2];
    const float* WQ  = (const float*)d_in[4];
    const float* bQ  = (const float*)d_in[5];
    const float* WK  = (const float*)d_in[6];
    const float* bK  = (const float*)d_in[7];
    const float* WV  = (const float*)d_in[8];
    const float* bV  = (const float*)d_in[9];
    const float* WO  = (const float*)d_in[10];
    const float* bO  = (const float*)d_in[11];
    const float* ln1w= (const float*)d_in[12];
    const float* ln1b= (const float*)d_in[13];
    const float* Wsw = (const float*)d_in[14];
    const float* bsw = (const float*)d_in[15];
    const float* W1  = (const float*)d_in[16];
    const float* b1  = (const float*)d_in[17];
    const float* W2  = (const float*)d_in[18];
    const float* b2  = (const float*)d_in[19];
    float* out = (float*)d_out;

    float *pQ, *pK, *pV, *pZ, *pzn, *peb, *ph, *py;
    int *proute, *ppos;
    cudaGetSymbolAddress((void**)&pQ,  g_Q);
    cudaGetSymbolAddress((void**)&pK,  g_K);
    cudaGetSymbolAddress((void**)&pV,  g_V);
    cudaGetSymbolAddress((void**)&pZ,  g_Z);
    cudaGetSymbolAddress((void**)&pzn, g_zn);
    cudaGetSymbolAddress((void**)&peb, g_eb);
    cudaGetSymbolAddress((void**)&ph,  g_h);
    cudaGetSymbolAddress((void**)&py,  g_y);
    cudaGetSymbolAddress((void**)&proute, g_route);
    cudaGetSymbolAddress((void**)&ppos,   g_pos);

    dim3 gemmGrid(CC/128, NTOK/128);   // (8, 64)
    sgemm_xt<<<gemmGrid, 256>>>(qx, WQ, bQ, pQ, NTOK, CC, CC);
    sgemm_xt<<<gemmGrid, 256>>>(kx, WK, bK, pK, NTOK, CC, CC);
    sgemm_xt<<<gemmGrid, 256>>>(vx, WV, bV, pV, NTOK, CC, CC);

    attn_kernel<<<dim3(LL/64, BB*HH), 256>>>(pQ, pK, pV, pZ);

    sgemm_xt<<<gemmGrid, 256>>>(pZ, WO, bO, pQ, NTOK, CC, CC);

    add_ln_kernel<<<NTOK, 256>>>(qx, pQ, ln1w, ln1b, pzn);
    router_kernel<<<NTOK, 128>>>(pzn, Wsw, bsw, proute);
    scanpos_kernel<<<EE, 256>>>(proute, ppos);
    gather_kernel<<<NTOK, 256>>>(pzn, proute, ppos, peb);
    ffn1_kernel<<<EE * (CAPP/4), 256>>>(peb, W1, b1, ph);
    ffn2_kernel<<<EE * (CAPP/4), 256>>>(ph, W2, b2, py);
    finalize_kernel<<<NTOK, 256>>>(pzn, py, proute, ppos, out);

    long long os = (long long)out_size;
    if (os >= (long long)(2 * NCE)) {
        cudaMemcpyAsync(out + NCE, kx, NCE * sizeof(float),
                        cudaMemcpyDeviceToDevice, 0);
    }
    if (os >= (long long)(3 * NCE)) {
        cudaMemcpyAsync(out + 2 * NCE, vx, NCE * sizeof(float),
                        cudaMemcpyDeviceToDevice, 0);
    }
    long long rem = os - (long long)(3 * NCE);
    if (rem > 0) {
        fill_ones_kernel<<<(int)((rem + 255) / 256), 256>>>(out + 3 * NCE, (int)rem);
    }
}

// round 4
// speedup vs baseline: 1.1550x; 1.1331x over previous
#include <cuda_runtime.h>
#include <cuda_bf16.h>
#include <math.h>
#include <stdint.h>

// ---------------- problem constants ----------------
#define BB 8
#define LL 1024
#define CC 1024
#define HH 16
#define DKK 64
#define NTOK (BB*LL)            // 8192
#define EE 16
#define HIDD 64
#define CAPP 256
#define NCE ((size_t)NTOK * CC)

typedef unsigned long long ull;

// ---------------- f32x2 helpers (attention) ----------------
__device__ __forceinline__ ull pk2(float x, float y) {
    ull r; asm("mov.b64 %0, {%1,%2};" : "=l"(r) : "f"(x), "f"(y)); return r;
}
__device__ __forceinline__ void upk2(ull v, float& x, float& y) {
    asm("mov.b64 {%0,%1}, %2;" : "=f"(x), "=f"(y) : "l"(v));
}
#define FFMA2(d, a, b) asm("fma.rn.f32x2 %0, %1, %2, %0;" : "+l"(d) : "l"(a), "l"(b))
#define FMUL2(d, a, b) asm("mul.rn.f32x2 %0, %1, %2;" : "=l"(d) : "l"(a), "l"(b))

// ---------------- baseline-PTX tensor-core helpers (sm_80+) ----------------
__device__ __forceinline__ uint32_t smem_u32(const void* p) {
    uint32_t a;
    asm("{ .reg .u64 t; cvta.to.shared.u64 t, %1; cvt.u32.u64 %0, t; }" : "=r"(a) : "l"(p));
    return a;
}
#define LDSM4(d0, d1, d2, d3, a) \
    asm volatile("ldmatrix.sync.aligned.m8n8.x4.shared.b16 {%0,%1,%2,%3}, [%4];" \
        : "=r"(d0), "=r"(d1), "=r"(d2), "=r"(d3) : "r"(a))
#define MMA16816(c, a0, a1, a2, a3, b0, b1) \
    asm volatile("mma.sync.aligned.m16n8k16.row.col.f32.bf16.bf16.f32 " \
        "{%0,%1,%2,%3}, {%4,%5,%6,%7}, {%8,%9}, {%0,%1,%2,%3};" \
        : "+f"((c)[0]), "+f"((c)[1]), "+f"((c)[2]), "+f"((c)[3]) \
        : "r"(a0), "r"(a1), "r"(a2), "r"(a3), "r"(b0), "r"(b1))
#define CP_ASYNC16(dst, src) \
    asm volatile("cp.async.cg.shared.global [%0], [%1], 16;" :: "r"(dst), "l"(src))
#define CP_COMMIT() asm volatile("cp.async.commit_group;" ::: "memory")
#define CP_WAIT1()  asm volatile("cp.async.wait_group 1;" ::: "memory")

// ---------------- scratch ----------------
__device__ float g_Q [NTOK * CC];
__device__ float g_K [NTOK * CC];
__device__ float g_V [NTOK * CC];
__device__ float g_Z [NTOK * CC];
__device__ float g_zn[NTOK * CC];
__device__ float g_eb[EE * CAPP * CC];
__device__ float g_h [EE * CAPP * HIDD];
__device__ float g_y [EE * CAPP * CC];
__device__ int   g_route[NTOK];
__device__ int   g_pos  [NTOK];
__device__ __nv_bfloat16 g_x0[NTOK * CC];
__device__ __nv_bfloat16 g_x1[NTOK * CC];
__device__ __nv_bfloat16 g_x2[NTOK * CC];
__device__ __nv_bfloat16 g_w0[CC * CC];
__device__ __nv_bfloat16 g_w1[CC * CC];
__device__ __nv_bfloat16 g_w2[CC * CC];

// ---------------- fp32 -> 3x bf16 split ----------------
__global__ void __launch_bounds__(256)
split3_kernel(const float* __restrict__ in, __nv_bfloat16* __restrict__ o0,
              __nv_bfloat16* __restrict__ o1, __nv_bfloat16* __restrict__ o2, int n4)
{
    int i = blockIdx.x * 256 + threadIdx.x;
    if (i >= n4) return;
    float4 v = ((const float4*)in)[i];
    float a[4] = {v.x, v.y, v.z, v.w};
    union { __nv_bfloat16 b[4]; uint2 u; } s0, s1, s2;
    #pragma unroll
    for (int j = 0; j < 4; j++) {
        __nv_bfloat16 h = __float2bfloat16(a[j]);
        float r1 = a[j] - __bfloat162float(h);
        __nv_bfloat16 m = __float2bfloat16(r1);
        float r2 = r1 - __bfloat162float(m);
        __nv_bfloat16 l = __float2bfloat16(r2);
        s0.b[j] = h; s1.b[j] = m; s2.b[j] = l;
    }
    ((uint2*)o0)[i] = s0.u;
    ((uint2*)o1)[i] = s1.u;
    ((uint2*)o2)[i] = s2.u;
}

// ---------------- HMMA GEMM: Y[M,N] = X[M,K] @ W[N,K]^T + bias ----------------
// 128x128 CTA tile, 8 warps (64x32 each), BK=32 bf16, 3-stage cp.async pipeline.
// Virtual K' = 6*1024 over the 6 split products (exact fp32 emulation to ~2^-26).
#define APAD 40                    // padded bf16 row stride (80B; conflict-free LDSM)
#define A_BYTES (128 * APAD * 2)   // 10240
#define STAGE_BYTES (2 * A_BYTES)  // 20480
#define GEMM_SMEM (3 * STAGE_BYTES)
#define NCH 192                    // 6144 / 32

__global__ void __launch_bounds__(256)
mma_gemm(const __nv_bfloat16* __restrict__ X0, const __nv_bfloat16* __restrict__ X1,
         const __nv_bfloat16* __restrict__ X2,
         const __nv_bfloat16* __restrict__ W0, const __nv_bfloat16* __restrict__ W1,
         const __nv_bfloat16* __restrict__ W2,
         const float* __restrict__ bias, float* __restrict__ Y)
{
    extern __shared__ char smem[];
    const uint32_t sb = smem_u32(smem);
    const int tid = threadIdx.x, wid = tid >> 5, lane = tid & 31;
    const int bm = blockIdx.y * 128, bn = blockIdx.x * 128;
    const int wm = (wid >> 2) * 64;      // warp row offset in tile
    const int wn = (wid & 3) * 32;       // warp col offset in tile

    const __nv_bfloat16* SA[6] = {X0, X0, X1, X1, X0, X2};
    const __nv_bfloat16* SB[6] = {W0, W1, W0, W1, W2, W0};

    // per-thread global-load coords (2 x 16B per matrix per stage)
    const int r0 = tid >> 2,        c0 = (tid & 3) * 8;
    const int r1 = (tid + 256) >> 2, c1 = ((tid + 256) & 3) * 8;

    #define LOAD_STAGE(sbuf, ch) do { \
        int p_ = (ch) >> 5; \
        int ko_ = ((ch) & 31) << 5; \
        const __nv_bfloat16* ga_ = SA[p_]; \
        const __nv_bfloat16* gb_ = SB[p_]; \
        uint32_t dA_ = sb + (sbuf) * STAGE_BYTES; \
        uint32_t dB_ = dA_ + A_BYTES; \
        CP_ASYNC16(dA_ + (r0 * APAD + c0) * 2, ga_ + (size_t)(bm + r0) * CC + ko_ + c0); \
        CP_ASYNC16(dA_ + (r1 * APAD + c1) * 2, ga_ + (size_t)(bm + r1) * CC + ko_ + c1); \
        CP_ASYNC16(dB_ + (r0 * APAD + c0) * 2, gb_ + (size_t)(bn + r0) * CC + ko_ + c0); \
        CP_ASYNC16(dB_ + (r1 * APAD + c1) * 2, gb_ + (size_t)(bn + r1) * CC + ko_ + c1); \
    } while (0)

    float acc[4][4][4];
    #pragma unroll
    for (int i = 0; i < 4; i++)
        #pragma unroll
        for (int j = 0; j < 4; j++)
            #pragma unroll
            for (int q = 0; q < 4; q++) acc[i][j][q] = 0.f;

    LOAD_STAGE(0, 0); CP_COMMIT();
    LOAD_STAGE(1, 1); CP_COMMIT();

    int sidx = 0;   // stage index = c % 3
    for (int c = 0; c < NCH; c++) {
        CP_WAIT1();
        __syncthreads();
        // prefetch stage c+2 into buffer (c+2)%3 (all warps are past compute of c-1)
        if (c + 2 < NCH) {
            int nb = sidx + 2; if (nb >= 3) nb -= 3;
            LOAD_STAGE(nb, c + 2);
        }
        CP_COMMIT();

        uint32_t sA = sb + sidx * STAGE_BYTES;
        uint32_t sB = sA + A_BYTES;
        #pragma unroll
        for (int kk = 0; kk < 2; kk++) {
            uint32_t a[4][4];
            #pragma unroll
            for (int i = 0; i < 4; i++) {
                int arow = wm + i * 16 + (lane & 15);
                int acol = kk * 16 + ((lane >> 4) << 3);
                LDSM4(a[i][0], a[i][1], a[i][2], a[i][3],
                      sA + (uint32_t)(arow * APAD + acol) * 2);
            }
            #pragma unroll
            for (int jp = 0; jp < 2; jp++) {
                uint32_t b0, b1, b2, b3;
                int g = lane >> 3;
                int brow = wn + jp * 16 + ((g & 2) << 2) + (lane & 7);
                int bcol = kk * 16 + ((g & 1) << 3);
                LDSM4(b0, b1, b2, b3, sB + (uint32_t)(brow * APAD + bcol) * 2);
                #pragma unroll
                for (int i = 0; i < 4; i++) {
                    MMA16816(acc[i][2*jp],   a[i][0], a[i][1], a[i][2], a[i][3], b0, b1);
                    MMA16816(acc[i][2*jp+1], a[i][0], a[i][1], a[i][2], a[i][3], b2, b3);
                }
            }
        }
        __syncthreads();
        sidx++; if (sidx >= 3) sidx = 0;
    }

    // epilogue: add bias, write fp32
    #pragma unroll
    for (int i = 0; i < 4; i++) {
        int row = bm + wm + i * 16 + (lane >> 2);
        #pragma unroll
        for (int j = 0; j < 4; j++) {
            int col = bn + wn + j * 8 + ((lane & 3) << 1);
            float bx = bias[col], by = bias[col + 1];
            float2 v0 = {acc[i][j][0] + bx, acc[i][j][1] + by};
            float2 v1 = {acc[i][j][2] + bx, acc[i][j][3] + by};
            *(float2*)(Y + (size_t)row * CC + col) = v0;
            *(float2*)(Y + (size_t)(row + 8) * CC + col) = v1;
        }
    }
    #undef LOAD_STAGE
}

// ---------------- flash attention (fp32, f32x2 inner math) ----------------
__global__ void __launch_bounds__(256)
attn_kernel(const float* __restrict__ Q, const float* __restrict__ K,
            const float* __restrict__ V, float* __restrict__ Z)
{
    __shared__ float Qs[64][68];
    __shared__ float Ks[32][68];
    __shared__ float Vs[32][68];
    __shared__ float Ss[64][33];
    int tid = threadIdx.x;
    int tx = tid & 15, ty = tid >> 4;
    int bh = blockIdx.y;
    int b = bh >> 4, hh = bh & 15;
    int q0 = blockIdx.x * 64;
    size_t baseq = ((size_t)(b*LL + q0)) * CC + hh*DKK;

    for (int i = tid; i < 64*16; i += 256) {
        int r = i >> 4, c4 = (i & 15) * 4;
        *(float4*)&Qs[r][c4] = *(const float4*)(Q + baseq + (size_t)r*CC + c4);
    }

    ull accp[4][2];
    #pragma unroll
    for (int i = 0; i < 4; i++) { accp[i][0] = 0ull; accp[i][1] = 0ull; }
    float m_i[4], l_i[4];
    #pragma unroll
    for (int i = 0; i < 4; i++) { m_i[i] = -1e30f; l_i[i] = 0.f; }

    for (int kt = 0; kt < LL/32; kt++) {
        __syncthreads();
        size_t basek = ((size_t)(b*LL + kt*32)) * CC + hh*DKK;
        for (int i = tid; i < 32*16; i += 256) {
            int r = i >> 4, c4 = (i & 15) * 4;
            *(float4*)&Ks[r][c4] = *(const float4*)(K + basek + (size_t)r*CC + c4);
            *(float4*)&Vs[r][c4] = *(const float4*)(V + basek + (size_t)r*CC + c4);
        }
        __syncthreads();

        ull s2[4][2];
        #pragma unroll
        for (int i = 0; i < 4; i++) { s2[i][0] = 0ull; s2[i][1] = 0ull; }
        #pragma unroll
        for (int d4 = 0; d4 < 16; d4++) {
            float4 qv[4], kv[2];
            #pragma unroll
            for (int i = 0; i < 4; i++) qv[i] = *(float4*)&Qs[ty*4+i][d4*4];
            #pragma unroll
            for (int j = 0; j < 2; j++) kv[j] = *(float4*)&Ks[tx + 16*j][d4*4];
            ull kp[2][2];
            kp[0][0] = *reinterpret_cast<ull*>(&kv[0].x);
            kp[0][1] = *reinterpret_cast<ull*>(&kv[0].z);
            kp[1][0] = *reinterpret_cast<ull*>(&kv[1].x);
            kp[1][1] = *reinterpret_cast<ull*>(&kv[1].z);
            #pragma unroll
            for (int i = 0; i < 4; i++) {
                ull qp0 = *reinterpret_cast<ull*>(&qv[i].x);
                ull qp1 = *reinterpret_cast<ull*>(&qv[i].z);
                FFMA2(s2[i][0], qp0, kp[0][0]);
                FFMA2(s2[i][0], qp1, kp[0][1]);
                FFMA2(s2[i][1], qp0, kp[1][0]);
                FFMA2(s2[i][1], qp1, kp[1][1]);
            }
        }

        #pragma unroll
        for (int i = 0; i < 4; i++) {
            float a0, a1, b0, b1;
            upk2(s2[i][0], a0, a1);
            upk2(s2[i][1], b0, b1);
            float s0 = (a0 + a1) * 0.125f;
            float s1 = (b0 + b1) * 0.125f;
            float mt = fmaxf(s0, s1);
            #pragma unroll
            for (int o = 8; o; o >>= 1)
                mt = fmaxf(mt, __shfl_xor_sync(0xffffffffu, mt, o, 16));
            float mn = fmaxf(m_i[i], mt);
            float al = __expf(m_i[i] - mn);
            float p0 = __expf(s0 - mn);
            float p1 = __expf(s1 - mn);
            float rs = p0 + p1;
            #pragma unroll
            for (int o = 8; o; o >>= 1)
                rs += __shfl_xor_sync(0xffffffffu, rs, o, 16);
            l_i[i] = l_i[i] * al + rs;
            m_i[i] = mn;
            Ss[ty*4+i][tx]      = p0;
            Ss[ty*4+i][tx + 16] = p1;
            ull alp = pk2(al, al);
            FMUL2(accp[i][0], accp[i][0], alp);
            FMUL2(accp[i][1], accp[i][1], alp);
        }
        __syncthreads();

        #pragma unroll 8
        for (int kk = 0; kk < 32; kk++) {
            float4 vv = *(float4*)&Vs[kk][tx*4];
            ull vp0 = *reinterpret_cast<ull*>(&vv.x);
            ull vp1 = *reinterpret_cast<ull*>(&vv.z);
            #pragma unroll
            for (int i = 0; i < 4; i++) {
                float p = Ss[ty*4+i][kk];
                ull pp = pk2(p, p);
                FFMA2(accp[i][0], pp, vp0);
                FFMA2(accp[i][1], pp, vp1);
            }
        }
    }

    #pragma unroll
    for (int i = 0; i < 4; i++) {
        float inv = 1.f / l_i[i];
        float4 o;
        upk2(accp[i][0], o.x, o.y);
        upk2(accp[i][1], o.z, o.w);
        o.x *= inv; o.y *= inv; o.z *= inv; o.w *= inv;
        *(float4*)(Z + baseq + (size_t)(ty*4+i)*CC + tx*4) = o;
    }
}

// ---------------- block reduce helper ----------------
__device__ __forceinline__ float blockReduceSum256(float v, float* red)
{
    int lane = threadIdx.x & 31, warp = threadIdx.x >> 5;
    #pragma unroll
    for (int o = 16; o; o >>= 1) v += __shfl_xor_sync(0xffffffffu, v, o);
    if (lane == 0) red[warp] = v;
    __syncthreads();
    if (warp == 0) {
        v = (lane < 8) ? red[lane] : 0.f;
        #pragma unroll
        for (int o = 4; o; o >>= 1) v += __shfl_xor_sync(0xffffffffu, v, o);
        if (lane == 0) red[0] = v;
    }
    __syncthreads();
    float r = red[0];
    __syncthreads();
    return r;
}

// ---------------- residual add + LayerNorm ----------------
__global__ void __launch_bounds__(256)
add_ln_kernel(const float* __restrict__ qx, const float* __restrict__ att,
              const float* __restrict__ w, const float* __restrict__ bb,
              float* __restrict__ zn)
{
    __shared__ float red[8];
    int row = blockIdx.x, tid = threadIdx.x;
    const float4* xq = (const float4*)(qx  + (size_t)row * CC);
    const float4* aq = (const float4*)(att + (size_t)row * CC);
    float4 x = xq[tid], a = aq[tid];
    float4 v; v.x = x.x + a.x; v.y = x.y + a.y; v.z = x.z + a.z; v.w = x.w + a.w;
    float mean = blockReduceSum256(v.x + v.y + v.z + v.w, red) * (1.f/1024.f);
    float dx = v.x - mean, dy = v.y - mean, dz = v.z - mean, dw = v.w - mean;
    float var = blockReduceSum256(dx*dx + dy*dy + dz*dz + dw*dw, red) * (1.f/1024.f);
    float rs = rsqrtf(var + 1e-5f);
    float4 wv = ((const float4*)w)[tid];
    float4 bv = ((const float4*)bb)[tid];
    float4 o;
    o.x = dx*rs*wv.x + bv.x; o.y = dy*rs*wv.y + bv.y;
    o.z = dz*rs*wv.z + bv.z; o.w = dw*rs*wv.w + bv.w;
    ((float4*)(zn + (size_t)row * CC))[tid] = o;
}

// ---------------- router: argmax of logits ----------------
__global__ void __launch_bounds__(128)
router_kernel(const float* __restrict__ zn, const float* __restrict__ Wsw,
              const float* __restrict__ bsw, int* __restrict__ route)
{
    int tok = blockIdx.x, tid = threadIdx.x;
    int lane = tid & 31, warp = tid >> 5;
    float part[EE] = {};
    for (int c = tid; c < CC; c += 128) {
        float xv = zn[(size_t)tok * CC + c];
        #pragma unroll
        for (int e = 0; e < EE; e++) part[e] += xv * Wsw[e*CC + c];
    }
    __shared__ float wsum[4][EE];
    #pragma unroll
    for (int e = 0; e < EE; e++) {
        float v = part[e];
        #pragma unroll
        for (int o = 16; o; o >>= 1) v += __shfl_xor_sync(0xffffffffu, v, o);
        if (lane == 0) wsum[warp][e] = v;
    }
    __syncthreads();
    if (tid == 0) {
        float best = -1e30f; int bi = 0;
        #pragma unroll
        for (int e = 0; e < EE; e++) {
            float lg = wsum[0][e] + wsum[1][e] + wsum[2][e] + wsum[3][e] + bsw[e];
            if (lg > best) { best = lg; bi = e; }
        }
        route[tok] = bi;
    }
}

// ---------------- deterministic per-expert prefix positions ----------------
__global__ void __launch_bounds__(256)
scanpos_kernel(const int* __restrict__ route, int* __restrict__ pos)
{
    int e = blockIdx.x;
    int tid = threadIdx.x;
    int lane = tid & 31, warp = tid >> 5;
    __shared__ int wtot[8];
    __shared__ int running;
    if (tid == 0) running = 0;
    __syncthreads();
    for (int base = 0; base < NTOK; base += 256) {
        int tok = base + tid;
        int flag = (route[tok] == e);
        unsigned m = __ballot_sync(0xffffffffu, flag);
        int rank = __popc(m & ((1u << lane) - 1u));
        if (lane == 31) wtot[warp] = __popc(m);
        __syncthreads();
        int prefix = 0;
        for (int w = 0; w < warp; w++) prefix += wtot[w];
        if (flag) pos[tok] = running + prefix + rank;
        __syncthreads();
        if (tid == 0) {
            int t = 0;
            for (int w = 0; w < 8; w++) t += wtot[w];
            running += t;
        }
        __syncthreads();
    }
}

// ---------------- gather kept tokens into expert buffers ----------------
__global__ void __launch_bounds__(256)
gather_kernel(const float* __restrict__ zn, const int* __restrict__ route,
              const int* __restrict__ pos, float* __restrict__ eb)
{
    int tok = blockIdx.x;
    int p = pos[tok];
    if (p >= CAPP) return;
    size_t slot = (size_t)route[tok] * CAPP + p;
    ((float4*)(eb + slot * CC))[threadIdx.x] =
        ((const float4*)(zn + (size_t)tok * CC))[threadIdx.x];
}

// ---------------- expert FFN layer 1 ----------------
__global__ void __launch_bounds__(256)
ffn1_kernel(const float* __restrict__ eb, const float* __restrict__ W1,
            const float* __restrict__ b1, float* __restrict__ h)
{
    int blk = blockIdx.x;
    int e  = blk >> 6;
    int r0 = (blk & 63) * 4;
    __shared__ float xs[4][CC];
    __shared__ float red[4][4][HIDD];
    int tid = threadIdx.x;
    const float4* src = (const float4*)(eb + ((size_t)e*CAPP + r0) * CC);
    for (int i = tid; i < 4 * (CC/4); i += 256)
        ((float4*)xs)[i] = src[i];
    __syncthreads();
    int kp = tid >> 6;
    int n  = tid & 63;
    float acc[4] = {};
    const float* w = W1 + (size_t)e * CC * HIDD + n;
    #pragma unroll 4
    for (int k = kp; k < CC; k += 4) {
        float wv = w[(size_t)k * HIDD];
        #pragma unroll
        for (int r = 0; r < 4; r++) acc[r] += xs[r][k] * wv;
    }
    #pragma unroll
    for (int r = 0; r < 4; r++) red[kp][r][n] = acc[r];
    __syncthreads();
    {
        int r = tid >> 6, n2 = tid & 63;
        float s = red[0][r][n2] + red[1][r][n2] + red[2][r][n2] + red[3][r][n2]
                + b1[e*HIDD + n2];
        h[((size_t)e*CAPP + r0 + r) * HIDD + n2] = fmaxf(s, 0.f);
    }
}

// ---------------- expert FFN layer 2 ----------------
__global__ void __launch_bounds__(256)
ffn2_kernel(const float* __restrict__ h, const float* __restrict__ W2,
            const float* __restrict__ b2, float* __restrict__ y)
{
    int blk = blockIdx.x;
    int e  = blk >> 6;
    int r0 = (blk & 63) * 4;
    __shared__ float hs[4][HIDD];
    int tid = threadIdx.x;
    hs[tid >> 6][tid & 63] = h[((size_t)e*CAPP + r0 + (tid >> 6)) * HIDD + (tid & 63)];
    __syncthreads();
    int c = tid * 4;
    float4 acc[4];
    #pragma unroll
    for (int r = 0; r < 4; r++) { acc[r].x=0.f; acc[r].y=0.f; acc[r].z=0.f; acc[r].w=0.f; }
    const float* w = W2 + (size_t)e * HIDD * CC + c;
    #pragma unroll 8
    for (int k = 0; k < HIDD; k++) {
        float4 wv = *(const float4*)(w + (size_t)k * CC);
        #pragma unroll
        for (int r = 0; r < 4; r++) {
            float hv = hs[r][k];
            acc[r].x += hv*wv.x; acc[r].y += hv*wv.y;
            acc[r].z += hv*wv.z; acc[r].w += hv*wv.w;
        }
    }
    float4 bb = *(const float4*)(b2 + (size_t)e * CC + c);
    #pragma unroll
    for (int r = 0; r < 4; r++) {
        float4 o;
        o.x = acc[r].x + bb.x; o.y = acc[r].y + bb.y;
        o.z = acc[r].z + bb.z; o.w = acc[r].w + bb.w;
        *(float4*)(y + ((size_t)e*CAPP + r0 + r) * CC + c) = o;
    }
}

// ---------------- final: out = zn + (kept ? y[slot] : zn) ----------------
__global__ void __launch_bounds__(256)
finalize_kernel(const float* __restrict__ zn, const float* __restrict__ y,
                const int* __restrict__ route, const int* __restrict__ pos,
                float* __restrict__ out)
{
    int tok = blockIdx.x, tid = threadIdx.x;
    int p = pos[tok];
    float4 z = ((const float4*)(zn + (size_t)tok * CC))[tid];
    float4 o;
    if (p < CAPP) {
        float4 yv = ((const float4*)(y + ((size_t)route[tok]*CAPP + p) * CC))[tid];
        o.x = z.x + yv.x; o.y = z.y + yv.y; o.z = z.z + yv.z; o.w = z.w + yv.w;
    } else {
        o.x = 2.f*z.x; o.y = 2.f*z.y; o.z = 2.f*z.z; o.w = 2.f*z.w;
    }
    ((float4*)(out + (size_t)tok * CC))[tid] = o;
}

__global__ void fill_ones_kernel(float* __restrict__ p, int n)
{
    int i = blockIdx.x * 256 + threadIdx.x;
    if (i < n) p[i] = 1.0f;
}

// ---------------- launch ----------------
extern "C" void kernel_launch(void* const* d_in, const int* in_sizes, int n_in,
                              void* d_out, int out_size)
{
    const float* qx  = (const float*)d_in[0];
    const float* kx  = (const float*)d_in[1];
    const float* vx  = (const float*)d_in[2];
    const float* WQ  = (const float*)d_in[4];
    const float* bQ  = (const float*)d_in[5];
    const float* WK  = (const float*)d_in[6];
    const float* bK  = (const float*)d_in[7];
    const float* WV  = (const float*)d_in[8];
    const float* bV  = (const float*)d_in[9];
    const float* WO  = (const float*)d_in[10];
    const float* bO  = (const float*)d_in[11];
    const float* ln1w= (const float*)d_in[12];
    const float* ln1b= (const float*)d_in[13];
    const float* Wsw = (const float*)d_in[14];
    const float* bsw = (const float*)d_in[15];
    const float* W1  = (const float*)d_in[16];
    const float* b1  = (const float*)d_in[17];
    const float* W2  = (const float*)d_in[18];
    const float* b2  = (const float*)d_in[19];
    float* out = (float*)d_out;

    float *pQ, *pK, *pV, *pZ, *pzn, *peb, *ph, *py;
    int *proute, *ppos;
    __nv_bfloat16 *px0, *px1, *px2, *pw0, *pw1, *pw2;
    cudaGetSymbolAddress((void**)&pQ,  g_Q);
    cudaGetSymbolAddress((void**)&pK,  g_K);
    cudaGetSymbolAddress((void**)&pV,  g_V);
    cudaGetSymbolAddress((void**)&pZ,  g_Z);
    cudaGetSymbolAddress((void**)&pzn, g_zn);
    cudaGetSymbolAddress((void**)&peb, g_eb);
    cudaGetSymbolAddress((void**)&ph,  g_h);
    cudaGetSymbolAddress((void**)&py,  g_y);
    cudaGetSymbolAddress((void**)&proute, g_route);
    cudaGetSymbolAddress((void**)&ppos,   g_pos);
    cudaGetSymbolAddress((void**)&px0, g_x0);
    cudaGetSymbolAddress((void**)&px1, g_x1);
    cudaGetSymbolAddress((void**)&px2, g_x2);
    cudaGetSymbolAddress((void**)&pw0, g_w0);
    cudaGetSymbolAddress((void**)&pw1, g_w1);
    cudaGetSymbolAddress((void**)&pw2, g_w2);

    cudaFuncSetAttribute(mma_gemm, cudaFuncAttributeMaxDynamicSharedMemorySize,
                         GEMM_SMEM);

    const int NX4 = NTOK * CC / 4;   // 2097152
    const int NW4 = CC * CC / 4;     // 262144
    dim3 gemmGrid(CC/128, NTOK/128); // (8, 64)

    // Q projection
    split3_kernel<<<NX4/256, 256>>>(qx, px0, px1, px2, NX4);
    split3_kernel<<<NW4/256, 256>>>(WQ, pw0, pw1, pw2, NW4);
    mma_gemm<<<gemmGrid, 256, GEMM_SMEM>>>(px0, px1, px2, pw0, pw1, pw2, bQ, pQ);
    // K projection
    split3_kernel<<<NX4/256, 256>>>(kx, px0, px1, px2, NX4);
    split3_kernel<<<NW4/256, 256>>>(WK, pw0, pw1, pw2, NW4);
    mma_gemm<<<gemmGrid, 256, GEMM_SMEM>>>(px0, px1, px2, pw0, pw1, pw2, bK, pK);
    // V projection
    split3_kernel<<<NX4/256, 256>>>(vx, px0, px1, px2, NX4);
    split3_kernel<<<NW4/256, 256>>>(WV, pw0, pw1, pw2, NW4);
    mma_gemm<<<gemmGrid, 256, GEMM_SMEM>>>(px0, px1, px2, pw0, pw1, pw2, bV, pV);

    attn_kernel<<<dim3(LL/64, BB*HH), 256>>>(pQ, pK, pV, pZ);

    // WO projection (reuse g_Q as attention-output buffer)
    split3_kernel<<<NX4/256, 256>>>(pZ, px0, px1, px2, NX4);
    split3_kernel<<<NW4/256, 256>>>(WO, pw0, pw1, pw2, NW4);
    mma_gemm<<<gemmGrid, 256, GEMM_SMEM>>>(px0, px1, px2, pw0, pw1, pw2, bO, pQ);

    add_ln_kernel<<<NTOK, 256>>>(qx, pQ, ln1w, ln1b, pzn);
    router_kernel<<<NTOK, 128>>>(pzn, Wsw, bsw, proute);
    scanpos_kernel<<<EE, 256>>>(proute, ppos);
    gather_kernel<<<NTOK, 256>>>(pzn, proute, ppos, peb);
    ffn1_kernel<<<EE * (CAPP/4), 256>>>(peb, W1, b1, ph);
    ffn2_kernel<<<EE * (CAPP/4), 256>>>(ph, W2, b2, py);
    finalize_kernel<<<NTOK, 256>>>(pzn, py, proute, ppos, out);

    long long os = (long long)out_size;
    if (os >= (long long)(2 * NCE)) {
        cudaMemcpyAsync(out + NCE, kx, NCE * sizeof(float),
                        cudaMemcpyDeviceToDevice, 0);
    }
    if (os >= (long long)(3 * NCE)) {
        cudaMemcpyAsync(out + 2 * NCE, vx, NCE * sizeof(float),
                        cudaMemcpyDeviceToDevice, 0);
    }
    long long rem = os - (long long)(3 * NCE);
    if (rem > 0) {
        fill_ones_kernel<<<(int)((rem + 255) / 256), 256>>>(out + 3 * NCE, (int)rem);
    }
}

// round 5
// speedup vs baseline: 1.4502x; 1.2555x over previous
#include <cuda_runtime.h>
#include <cuda_bf16.h>
#include <math.h>
#include <stdint.h>

// ---------------- problem constants ----------------
#define BB 8
#define LL 1024
#define CC 1024
#define HH 16
#define DKK 64
#define NTOK (BB*LL)            // 8192
#define EE 16
#define HIDD 64
#define CAPP 256
#define NCE ((size_t)NTOK * CC)

// ---------------- baseline-PTX tensor-core helpers (sm_80+) ----------------
__device__ __forceinline__ uint32_t smem_u32(const void* p) {
    uint32_t a;
    asm("{ .reg .u64 t; cvta.to.shared.u64 t, %1; cvt.u32.u64 %0, t; }" : "=r"(a) : "l"(p));
    return a;
}
#define LDSM4(d0, d1, d2, d3, a) \
    asm volatile("ldmatrix.sync.aligned.m8n8.x4.shared.b16 {%0,%1,%2,%3}, [%4];" \
        : "=r"(d0), "=r"(d1), "=r"(d2), "=r"(d3) : "r"(a))
#define LDSM4T(d0, d1, d2, d3, a) \
    asm volatile("ldmatrix.sync.aligned.m8n8.x4.trans.shared.b16 {%0,%1,%2,%3}, [%4];" \
        : "=r"(d0), "=r"(d1), "=r"(d2), "=r"(d3) : "r"(a))
#define MMA16816(c, a0, a1, a2, a3, b0, b1) \
    asm volatile("mma.sync.aligned.m16n8k16.row.col.f32.bf16.bf16.f32 " \
        "{%0,%1,%2,%3}, {%4,%5,%6,%7}, {%8,%9}, {%0,%1,%2,%3};" \
        : "+f"((c)[0]), "+f"((c)[1]), "+f"((c)[2]), "+f"((c)[3]) \
        : "r"(a0), "r"(a1), "r"(a2), "r"(a3), "r"(b0), "r"(b1))
#define CP_ASYNC16(dst, src) \
    asm volatile("cp.async.cg.shared.global [%0], [%1], 16;" :: "r"(dst), "l"(src))
#define CP_COMMIT() asm volatile("cp.async.commit_group;" ::: "memory")
#define CP_WAIT1()  asm volatile("cp.async.wait_group 1;" ::: "memory")

// ---------------- scratch ----------------
__device__ float g_Q [NTOK * CC];
__device__ float g_K [NTOK * CC];
__device__ float g_V [NTOK * CC];
__device__ float g_Z [NTOK * CC];
__device__ float g_zn[NTOK * CC];
__device__ float g_eb[EE * CAPP * CC];
__device__ float g_h [EE * CAPP * HIDD];
__device__ float g_y [EE * CAPP * CC];
__device__ int   g_route[NTOK];
__device__ int   g_pos  [NTOK];
__device__ __nv_bfloat16 g_x0[NTOK * CC];
__device__ __nv_bfloat16 g_x1[NTOK * CC];
__device__ __nv_bfloat16 g_x2[NTOK * CC];
__device__ __nv_bfloat16 g_w0[CC * CC];
__device__ __nv_bfloat16 g_w1[CC * CC];
__device__ __nv_bfloat16 g_w2[CC * CC];
// attention operand splits (projected Q/K/V)
__device__ __nv_bfloat16 g_q0[NTOK * CC];
__device__ __nv_bfloat16 g_q1[NTOK * CC];
__device__ __nv_bfloat16 g_q2[NTOK * CC];
__device__ __nv_bfloat16 g_k0[NTOK * CC];
__device__ __nv_bfloat16 g_k1[NTOK * CC];
__device__ __nv_bfloat16 g_k2[NTOK * CC];
__device__ __nv_bfloat16 g_v0[NTOK * CC];
__device__ __nv_bfloat16 g_v1[NTOK * CC];
__device__ __nv_bfloat16 g_v2[NTOK * CC];

// ---------------- fp32 -> 3x bf16 split ----------------
__global__ void __launch_bounds__(256)
split3_kernel(const float* __restrict__ in, __nv_bfloat16* __restrict__ o0,
              __nv_bfloat16* __restrict__ o1, __nv_bfloat16* __restrict__ o2, int n4)
{
    int i = blockIdx.x * 256 + threadIdx.x;
    if (i >= n4) return;
    float4 v = ((const float4*)in)[i];
    float a[4] = {v.x, v.y, v.z, v.w};
    union { __nv_bfloat16 b[4]; uint2 u; } s0, s1, s2;
    #pragma unroll
    for (int j = 0; j < 4; j++) {
        __nv_bfloat16 h = __float2bfloat16(a[j]);
        float r1 = a[j] - __bfloat162float(h);
        __nv_bfloat16 m = __float2bfloat16(r1);
        float r2 = r1 - __bfloat162float(m);
        __nv_bfloat16 l = __float2bfloat16(r2);
        s0.b[j] = h; s1.b[j] = m; s2.b[j] = l;
    }
    ((uint2*)o0)[i] = s0.u;
    ((uint2*)o1)[i] = s1.u;
    ((uint2*)o2)[i] = s2.u;
}

// ---------------- HMMA GEMM v2: 6 split tiles per real-K chunk ----------------
#define APAD 40                     // bf16 row stride (80B)
#define TILE_B (128 * APAD * 2)     // 10240
#define STAGE6 (6 * TILE_B)         // 61440
#define GEMM_SMEM (3 * STAGE6)      // 184320
#define NCHUNK 32                   // K=1024 / 32

__global__ void __launch_bounds__(256)
mma_gemm(const __nv_bfloat16* __restrict__ X0, const __nv_bfloat16* __restrict__ X1,
         const __nv_bfloat16* __restrict__ X2,
         const __nv_bfloat16* __restrict__ W0, const __nv_bfloat16* __restrict__ W1,
         const __nv_bfloat16* __restrict__ W2,
         const float* __restrict__ bias, float* __restrict__ Y)
{
    extern __shared__ char smem[];
    const uint32_t sb = smem_u32(smem);
    const int tid = threadIdx.x, wid = tid >> 5, lane = tid & 31;
    const int bm = blockIdx.y * 128, bn = blockIdx.x * 128;
    const int wm = (wid >> 2) * 64, wn = (wid & 3) * 32;

    const __nv_bfloat16* TS[6] = {X0, X1, X2, W0, W1, W2};

    #define G_LOAD(buf, ch) do { \
        int ko_ = (ch) * 32; \
        _Pragma("unroll") \
        for (int j_ = 0; j_ < 12; j_++) { \
            int e_ = j_ * 256 + tid; \
            int t_ = e_ >> 9; \
            int w_ = e_ & 511; \
            int r_ = w_ >> 2, c8_ = (w_ & 3) * 8; \
            int rowb_ = ((t_ < 3) ? bm : bn) + r_; \
            CP_ASYNC16(sb + (buf) * STAGE6 + t_ * TILE_B + (r_ * APAD + c8_) * 2, \
                       TS[t_] + (size_t)rowb_ * CC + ko_ + c8_); \
        } \
    } while (0)

    float acc[4][4][4];
    #pragma unroll
    for (int i = 0; i < 4; i++)
        #pragma unroll
        for (int j = 0; j < 4; j++)
            #pragma unroll
            for (int q = 0; q < 4; q++) acc[i][j][q] = 0.f;

    G_LOAD(0, 0); CP_COMMIT();
    G_LOAD(1, 1); CP_COMMIT();

    int sidx = 0;
    for (int c = 0; c < NCHUNK; c++) {
        CP_WAIT1();
        __syncthreads();
        if (c + 2 < NCHUNK) {
            int nb = sidx + 2; if (nb >= 3) nb -= 3;
            G_LOAD(nb, c + 2);
        }
        CP_COMMIT();

        uint32_t stage = sb + sidx * STAGE6;
        #pragma unroll
        for (int kk = 0; kk < 2; kk++) {
            uint32_t a[3][4][4];
            #pragma unroll
            for (int s = 0; s < 3; s++)
                #pragma unroll
                for (int i = 0; i < 4; i++) {
                    int arow = wm + i * 16 + (lane & 15);
                    int acol = kk * 16 + ((lane >> 4) << 3);
                    LDSM4(a[s][i][0], a[s][i][1], a[s][i][2], a[s][i][3],
                          stage + s * TILE_B + (uint32_t)(arow * APAD + acol) * 2);
                }
            #pragma unroll
            for (int jp = 0; jp < 2; jp++) {
                int g = lane >> 3;
                int brow = wn + jp * 16 + ((g & 2) << 2) + (lane & 7);
                int bcol = kk * 16 + ((g & 1) << 3);
                uint32_t boff = (uint32_t)(brow * APAD + bcol) * 2;
                uint32_t b0, b1, b2, b3;
                // bj = 0 (W0): pairs with X0, X1, X2
                LDSM4(b0, b1, b2, b3, stage + 3 * TILE_B + boff);
                #pragma unroll
                for (int i = 0; i < 4; i++) {
                    MMA16816(acc[i][2*jp],   a[0][i][0],a[0][i][1],a[0][i][2],a[0][i][3], b0,b1);
                    MMA16816(acc[i][2*jp+1], a[0][i][0],a[0][i][1],a[0][i][2],a[0][i][3], b2,b3);
                    MMA16816(acc[i][2*jp],   a[1][i][0],a[1][i][1],a[1][i][2],a[1][i][3], b0,b1);
                    MMA16816(acc[i][2*jp+1], a[1][i][0],a[1][i][1],a[1][i][2],a[1][i][3], b2,b3);
                    MMA16816(acc[i][2*jp],   a[2][i][0],a[2][i][1],a[2][i][2],a[2][i][3], b0,b1);
                    MMA16816(acc[i][2*jp+1], a[2][i][0],a[2][i][1],a[2][i][2],a[2][i][3], b2,b3);
                }
                // bj = 1 (W1): pairs with X0, X1
                LDSM4(b0, b1, b2, b3, stage + 4 * TILE_B + boff);
                #pragma unroll
                for (int i = 0; i < 4; i++) {
                    MMA16816(acc[i][2*jp],   a[0][i][0],a[0][i][1],a[0][i][2],a[0][i][3], b0,b1);
                    MMA16816(acc[i][2*jp+1], a[0][i][0],a[0][i][1],a[0][i][2],a[0][i][3], b2,b3);
                    MMA16816(acc[i][2*jp],   a[1][i][0],a[1][i][1],a[1][i][2],a[1][i][3], b0,b1);
                    MMA16816(acc[i][2*jp+1], a[1][i][0],a[1][i][1],a[1][i][2],a[1][i][3], b2,b3);
                }
                // bj = 2 (W2): pairs with X0
                LDSM4(b0, b1, b2, b3, stage + 5 * TILE_B + boff);
                #pragma unroll
                for (int i = 0; i < 4; i++) {
                    MMA16816(acc[i][2*jp],   a[0][i][0],a[0][i][1],a[0][i][2],a[0][i][3], b0,b1);
                    MMA16816(acc[i][2*jp+1], a[0][i][0],a[0][i][1],a[0][i][2],a[0][i][3], b2,b3);
                }
            }
        }
        __syncthreads();
        sidx++; if (sidx >= 3) sidx = 0;
    }

    #pragma unroll
    for (int i = 0; i < 4; i++) {
        int row = bm + wm + i * 16 + (lane >> 2);
        #pragma unroll
        for (int j = 0; j < 4; j++) {
            int col = bn + wn + j * 8 + ((lane & 3) << 1);
            float bx = bias[col], by = bias[col + 1];
            float2 v0 = {acc[i][j][0] + bx, acc[i][j][1] + by};
            float2 v1 = {acc[i][j][2] + bx, acc[i][j][3] + by};
            *(float2*)(Y + (size_t)row * CC + col) = v0;
            *(float2*)(Y + (size_t)(row + 8) * CC + col) = v1;
        }
    }
    #undef G_LOAD
}

// ---------------- helper: fp32 -> 3 bf16 (register split) ----------------
__device__ __forceinline__ void split3r(float a, __nv_bfloat16& b0,
                                        __nv_bfloat16& b1, __nv_bfloat16& b2)
{
    b0 = __float2bfloat16(a);
    float r1 = a - __bfloat162float(b0);
    b1 = __float2bfloat16(r1);
    float r2 = r1 - __bfloat162float(b1);
    b2 = __float2bfloat16(r2);
}
__device__ __forceinline__ uint32_t pkbf(__nv_bfloat16 lo, __nv_bfloat16 hi)
{
    __nv_bfloat162 t = __halves2bfloat162(lo, hi);
    return *reinterpret_cast<uint32_t*>(&t);
}

// ---------------- flash attention on HMMA (6-product bf16 split) ----------------
// grid (L/128, B*H); 256 threads; warp = 16 Q rows; K-tile 64.
#define QTILE (128 * 72 * 2)    // 18432
#define KVTILE (64 * 72 * 2)    // 9216
#define AT_SOFF (3 * QTILE)     // 55296
#define AT_STG (6 * KVTILE)     // 55296
#define ATTN_SMEM (AT_SOFF + 2 * AT_STG)  // 165888

__global__ void __launch_bounds__(256)
attn_mma(const __nv_bfloat16* __restrict__ Q0, const __nv_bfloat16* __restrict__ Q1,
         const __nv_bfloat16* __restrict__ Q2,
         const __nv_bfloat16* __restrict__ K0, const __nv_bfloat16* __restrict__ K1,
         const __nv_bfloat16* __restrict__ K2,
         const __nv_bfloat16* __restrict__ V0, const __nv_bfloat16* __restrict__ V1,
         const __nv_bfloat16* __restrict__ V2,
         float* __restrict__ Z)
{
    extern __shared__ char smem[];
    const uint32_t sb = smem_u32(smem);
    const int tid = threadIdx.x, wid = tid >> 5, lane = tid & 31;
    const int bh = blockIdx.y;
    const int b = bh >> 4, hh = bh & 15;
    const int q0 = blockIdx.x * 128;

    const __nv_bfloat16* QS[3] = {Q0, Q1, Q2};
    const __nv_bfloat16* KS[3] = {K0, K1, K2};
    const __nv_bfloat16* VS[3] = {V0, V1, V2};

    // Q splits -> smem (once)
    #pragma unroll
    for (int j = 0; j < 12; j++) {
        int e = j * 256 + tid;
        int t = e >> 10;          // 128 rows * 8 per tile
        int w = e & 1023;
        int r = w >> 3, c = w & 7;
        CP_ASYNC16(sb + t * QTILE + (uint32_t)(r * 72 + c * 8) * 2,
                   QS[t] + (size_t)(b * LL + q0 + r) * CC + hh * 64 + c * 8);
    }

    #define KV_LOAD(buf, kt) do { \
        _Pragma("unroll") \
        for (int j_ = 0; j_ < 12; j_++) { \
            int e_ = j_ * 256 + tid; \
            int t_ = e_ >> 9;      /* 64 rows * 8 per tile */ \
            int w_ = e_ & 511; \
            int r_ = w_ >> 3, c_ = w_ & 7; \
            const __nv_bfloat16* src_ = (t_ < 3) ? KS[t_] : VS[t_ - 3]; \
            CP_ASYNC16(sb + AT_SOFF + (buf) * AT_STG + t_ * KVTILE + \
                       (uint32_t)(r_ * 72 + c_ * 8) * 2, \
                       src_ + (size_t)(b * LL + (kt) * 64 + r_) * CC + hh * 64 + c_ * 8); \
        } \
    } while (0)

    KV_LOAD(0, 0); CP_COMMIT();
    KV_LOAD(1, 1); CP_COMMIT();

    float pv[8][4];
    #pragma unroll
    for (int j = 0; j < 8; j++)
        #pragma unroll
        for (int q = 0; q < 4; q++) pv[j][q] = 0.f;
    float m0 = -1e30f, m1 = -1e30f, l0 = 0.f, l1 = 0.f;
    uint32_t qf[3][4][4];

    for (int kt = 0; kt < LL / 64; kt++) {
        CP_WAIT1();
        __syncthreads();
        if (kt == 0) {
            #pragma unroll
            for (int s = 0; s < 3; s++)
                #pragma unroll
                for (int ks = 0; ks < 4; ks++) {
                    int arow = wid * 16 + (lane & 15);
                    int acol = ks * 16 + ((lane >> 4) << 3);
                    LDSM4(qf[s][ks][0], qf[s][ks][1], qf[s][ks][2], qf[s][ks][3],
                          sb + s * QTILE + (uint32_t)(arow * 72 + acol) * 2);
                }
        }

        uint32_t sK = sb + AT_SOFF + (kt & 1) * AT_STG;
        uint32_t sV = sK + 3 * KVTILE;

        // ---- S = Q K^T (6 products, fp32 accum) ----
        float sacc[8][4];
        #pragma unroll
        for (int j = 0; j < 8; j++)
            #pragma unroll
            for (int q = 0; q < 4; q++) sacc[j][q] = 0.f;

        #pragma unroll
        for (int ks = 0; ks < 4; ks++) {
            #pragma unroll
            for (int ntp = 0; ntp < 4; ntp++) {
                int g = lane >> 3;
                int brow = ntp * 16 + ((g & 2) << 2) + (lane & 7);
                int bcol = ks * 16 + ((g & 1) << 3);
                uint32_t boff = (uint32_t)(brow * 72 + bcol) * 2;
                uint32_t b0, b1, b2, b3;
                LDSM4(b0, b1, b2, b3, sK + 0 * KVTILE + boff);   // K0: Q0,Q1,Q2
                MMA16816(sacc[2*ntp],   qf[0][ks][0],qf[0][ks][1],qf[0][ks][2],qf[0][ks][3], b0,b1);
                MMA16816(sacc[2*ntp+1], qf[0][ks][0],qf[0][ks][1],qf[0][ks][2],qf[0][ks][3], b2,b3);
                MMA16816(sacc[2*ntp],   qf[1][ks][0],qf[1][ks][1],qf[1][ks][2],qf[1][ks][3], b0,b1);
                MMA16816(sacc[2*ntp+1], qf[1][ks][0],qf[1][ks][1],qf[1][ks][2],qf[1][ks][3], b2,b3);
                MMA16816(sacc[2*ntp],   qf[2][ks][0],qf[2][ks][1],qf[2][ks][2],qf[2][ks][3], b0,b1);
                MMA16816(sacc[2*ntp+1], qf[2][ks][0],qf[2][ks][1],qf[2][ks][2],qf[2][ks][3], b2,b3);
                LDSM4(b0, b1, b2, b3, sK + 1 * KVTILE + boff);   // K1: Q0,Q1
                MMA16816(sacc[2*ntp],   qf[0][ks][0],qf[0][ks][1],qf[0][ks][2],qf[0][ks][3], b0,b1);
                MMA16816(sacc[2*ntp+1], qf[0][ks][0],qf[0][ks][1],qf[0][ks][2],qf[0][ks][3], b2,b3);
                MMA16816(sacc[2*ntp],   qf[1][ks][0],qf[1][ks][1],qf[1][ks][2],qf[1][ks][3], b0,b1);
                MMA16816(sacc[2*ntp+1], qf[1][ks][0],qf[1][ks][1],qf[1][ks][2],qf[1][ks][3], b2,b3);
                LDSM4(b0, b1, b2, b3, sK + 2 * KVTILE + boff);   // K2: Q0
                MMA16816(sacc[2*ntp],   qf[0][ks][0],qf[0][ks][1],qf[0][ks][2],qf[0][ks][3], b0,b1);
                MMA16816(sacc[2*ntp+1], qf[0][ks][0],qf[0][ks][1],qf[0][ks][2],qf[0][ks][3], b2,b3);
            }
        }

        // ---- online softmax ----
        float tm0 = -1e30f, tm1 = -1e30f;
        #pragma unroll
        for (int j = 0; j < 8; j++) {
            tm0 = fmaxf(tm0, fmaxf(sacc[j][0], sacc[j][1]));
            tm1 = fmaxf(tm1, fmaxf(sacc[j][2], sacc[j][3]));
        }
        tm0 = fmaxf(tm0, __shfl_xor_sync(0xffffffffu, tm0, 1));
        tm0 = fmaxf(tm0, __shfl_xor_sync(0xffffffffu, tm0, 2));
        tm1 = fmaxf(tm1, __shfl_xor_sync(0xffffffffu, tm1, 1));
        tm1 = fmaxf(tm1, __shfl_xor_sync(0xffffffffu, tm1, 2));
        tm0 *= 0.125f; tm1 *= 0.125f;
        float mn0 = fmaxf(m0, tm0), mn1 = fmaxf(m1, tm1);
        float al0 = __expf(m0 - mn0), al1 = __expf(m1 - mn1);
        m0 = mn0; m1 = mn1;

        float rs0 = 0.f, rs1 = 0.f;
        uint32_t pf[3][4][4];
        #pragma unroll
        for (int j = 0; j < 8; j++) {
            float p0 = __expf(sacc[j][0] * 0.125f - mn0);
            float p1 = __expf(sacc[j][1] * 0.125f - mn0);
            float p2 = __expf(sacc[j][2] * 0.125f - mn1);
            float p3 = __expf(sacc[j][3] * 0.125f - mn1);
            rs0 += p0 + p1; rs1 += p2 + p3;
            __nv_bfloat16 a0, a1, a2, b0v, b1v, b2v, c0, c1, c2, d0, d1, d2;
            split3r(p0, a0, a1, a2);
            split3r(p1, b0v, b1v, b2v);
            split3r(p2, c0, c1, c2);
            split3r(p3, d0, d1, d2);
            int ks = j >> 1, ri = (j & 1) * 2;
            pf[0][ks][ri]     = pkbf(a0, b0v);
            pf[0][ks][ri + 1] = pkbf(c0, d0);
            pf[1][ks][ri]     = pkbf(a1, b1v);
            pf[1][ks][ri + 1] = pkbf(c1, d1);
            pf[2][ks][ri]     = pkbf(a2, b2v);
            pf[2][ks][ri + 1] = pkbf(c2, d2);
        }
        rs0 += __shfl_xor_sync(0xffffffffu, rs0, 1);
        rs0 += __shfl_xor_sync(0xffffffffu, rs0, 2);
        rs1 += __shfl_xor_sync(0xffffffffu, rs1, 1);
        rs1 += __shfl_xor_sync(0xffffffffu, rs1, 2);
        l0 = l0 * al0 + rs0;
        l1 = l1 * al1 + rs1;
        #pragma unroll
        for (int j = 0; j < 8; j++) {
            pv[j][0] *= al0; pv[j][1] *= al0;
            pv[j][2] *= al1; pv[j][3] *= al1;
        }

        // ---- PV (6 products) ----
        #pragma unroll
        for (int ks = 0; ks < 4; ks++) {
            #pragma unroll
            for (int ntp = 0; ntp < 4; ntp++) {
                int g = lane >> 3;
                int vrow = ks * 16 + ((g & 1) << 3) + (lane & 7);
                int vcol = ntp * 16 + ((g >> 1) << 3);
                uint32_t voff = (uint32_t)(vrow * 72 + vcol) * 2;
                uint32_t v0, v1, v2, v3;
                LDSM4T(v0, v1, v2, v3, sV + 0 * KVTILE + voff);  // V0: P0,P1,P2
                MMA16816(pv[2*ntp],   pf[0][ks][0],pf[0][ks][1],pf[0][ks][2],pf[0][ks][3], v0,v1);
                MMA16816(pv[2*ntp+1], pf[0][ks][0],pf[0][ks][1],pf[0][ks][2],pf[0][ks][3], v2,v3);
                MMA16816(pv[2*ntp],   pf[1][ks][0],pf[1][ks][1],pf[1][ks][2],pf[1][ks][3], v0,v1);
                MMA16816(pv[2*ntp+1], pf[1][ks][0],pf[1][ks][1],pf[1][ks][2],pf[1][ks][3], v2,v3);
                MMA16816(pv[2*ntp],   pf[2][ks][0],pf[2][ks][1],pf[2][ks][2],pf[2][ks][3], v0,v1);
                MMA16816(pv[2*ntp+1], pf[2][ks][0],pf[2][ks][1],pf[2][ks][2],pf[2][ks][3], v2,v3);
                LDSM4T(v0, v1, v2, v3, sV + 1 * KVTILE + voff);  // V1: P0,P1
                MMA16816(pv[2*ntp],   pf[0][ks][0],pf[0][ks][1],pf[0][ks][2],pf[0][ks][3], v0,v1);
                MMA16816(pv[2*ntp+1], pf[0][ks][0],pf[0][ks][1],pf[0][ks][2],pf[0][ks][3], v2,v3);
                MMA16816(pv[2*ntp],   pf[1][ks][0],pf[1][ks][1],pf[1][ks][2],pf[1][ks][3], v0,v1);
                MMA16816(pv[2*ntp+1], pf[1][ks][0],pf[1][ks][1],pf[1][ks][2],pf[1][ks][3], v2,v3);
                LDSM4T(v0, v1, v2, v3, sV + 2 * KVTILE + voff);  // V2: P0
                MMA16816(pv[2*ntp],   pf[0][ks][0],pf[0][ks][1],pf[0][ks][2],pf[0][ks][3], v0,v1);
                MMA16816(pv[2*ntp+1], pf[0][ks][0],pf[0][ks][1],pf[0][ks][2],pf[0][ks][3], v2,v3);
            }
        }

        __syncthreads();
        if (kt + 2 < LL / 64) KV_LOAD(kt & 1, kt + 2);
        CP_COMMIT();
    }

    float inv0 = 1.f / l0, inv1 = 1.f / l1;
    int gr0 = b * LL + q0 + wid * 16 + (lane >> 2);
    #pragma unroll
    for (int j = 0; j < 8; j++) {
        int col = hh * 64 + j * 8 + ((lane & 3) << 1);
        float2 o0 = {pv[j][0] * inv0, pv[j][1] * inv0};
        float2 o1 = {pv[j][2] * inv1, pv[j][3] * inv1};
        *(float2*)(Z + (size_t)gr0 * CC + col) = o0;
        *(float2*)(Z + (size_t)(gr0 + 8) * CC + col) = o1;
    }
    #undef KV_LOAD
}

// ---------------- block reduce helper ----------------
__device__ __forceinline__ float blockReduceSum256(float v, float* red)
{
    int lane = threadIdx.x & 31, warp = threadIdx.x >> 5;
    #pragma unroll
    for (int o = 16; o; o >>= 1) v += __shfl_xor_sync(0xffffffffu, v, o);
    if (lane == 0) red[warp] = v;
    __syncthreads();
    if (warp == 0) {
        v = (lane < 8) ? red[lane] : 0.f;
        #pragma unroll
        for (int o = 4; o; o >>= 1) v += __shfl_xor_sync(0xffffffffu, v, o);
        if (lane == 0) red[0] = v;
    }
    __syncthreads();
    float r = red[0];
    __syncthreads();
    return r;
}

// ---------------- residual add + LayerNorm ----------------
__global__ void __launch_bounds__(256)
add_ln_kernel(const float* __restrict__ qx, const float* __restrict__ att,
              const float* __restrict__ w, const float* __restrict__ bb,
              float* __restrict__ zn)
{
    __shared__ float red[8];
    int row = blockIdx.x, tid = threadIdx.x;
    const float4* xq = (const float4*)(qx  + (size_t)row * CC);
    const float4* aq = (const float4*)(att + (size_t)row * CC);
    float4 x = xq[tid], a = aq[tid];
    float4 v; v.x = x.x + a.x; v.y = x.y + a.y; v.z = x.z + a.z; v.w = x.w + a.w;
    float mean = blockReduceSum256(v.x + v.y + v.z + v.w, red) * (1.f/1024.f);
    float dx = v.x - mean, dy = v.y - mean, dz = v.z - mean, dw = v.w - mean;
    float var = blockReduceSum256(dx*dx + dy*dy + dz*dz + dw*dw, red) * (1.f/1024.f);
    float rs = rsqrtf(var + 1e-5f);
    float4 wv = ((const float4*)w)[tid];
    float4 bv = ((const float4*)bb)[tid];
    float4 o;
    o.x = dx*rs*wv.x + bv.x; o.y = dy*rs*wv.y + bv.y;
    o.z = dz*rs*wv.z + bv.z; o.w = dw*rs*wv.w + bv.w;
    ((float4*)(zn + (size_t)row * CC))[tid] = o;
}

// ---------------- router: argmax of logits ----------------
__global__ void __launch_bounds__(128)
router_kernel(const float* __restrict__ zn, const float* __restrict__ Wsw,
              const float* __restrict__ bsw, int* __restrict__ route)
{
    int tok = blockIdx.x, tid = threadIdx.x;
    int lane = tid & 31, warp = tid >> 5;
    float part[EE] = {};
    for (int c = tid; c < CC; c += 128) {
        float xv = zn[(size_t)tok * CC + c];
        #pragma unroll
        for (int e = 0; e < EE; e++) part[e] += xv * Wsw[e*CC + c];
    }
    __shared__ float wsum[4][EE];
    #pragma unroll
    for (int e = 0; e < EE; e++) {
        float v = part[e];
        #pragma unroll
        for (int o = 16; o; o >>= 1) v += __shfl_xor_sync(0xffffffffu, v, o);
        if (lane == 0) wsum[warp][e] = v;
    }
    __syncthreads();
    if (tid == 0) {
        float best = -1e30f; int bi = 0;
        #pragma unroll
        for (int e = 0; e < EE; e++) {
            float lg = wsum[0][e] + wsum[1][e] + wsum[2][e] + wsum[3][e] + bsw[e];
            if (lg > best) { best = lg; bi = e; }
        }
        route[tok] = bi;
    }
}

// ---------------- deterministic per-expert prefix positions ----------------
__global__ void __launch_bounds__(256)
scanpos_kernel(const int* __restrict__ route, int* __restrict__ pos)
{
    int e = blockIdx.x;
    int tid = threadIdx.x;
    int lane = tid & 31, warp = tid >> 5;
    __shared__ int wtot[8];
    __shared__ int running;
    if (tid == 0) running = 0;
    __syncthreads();
    for (int base = 0; base < NTOK; base += 256) {
        int tok = base + tid;
        int flag = (route[tok] == e);
        unsigned m = __ballot_sync(0xffffffffu, flag);
        int rank = __popc(m & ((1u << lane) - 1u));
        if (lane == 31) wtot[warp] = __popc(m);
        __syncthreads();
        int prefix = 0;
        for (int w = 0; w < warp; w++) prefix += wtot[w];
        if (flag) pos[tok] = running + prefix + rank;
        __syncthreads();
        if (tid == 0) {
            int t = 0;
            for (int w = 0; w < 8; w++) t += wtot[w];
            running += t;
        }
        __syncthreads();
    }
}

// ---------------- gather kept tokens into expert buffers ----------------
__global__ void __launch_bounds__(256)
gather_kernel(const float* __restrict__ zn, const int* __restrict__ route,
              const int* __restrict__ pos, float* __restrict__ eb)
{
    int tok = blockIdx.x;
    int p = pos[tok];
    if (p >= CAPP) return;
    size_t slot = (size_t)route[tok] * CAPP + p;
    ((float4*)(eb + slot * CC))[threadIdx.x] =
        ((const float4*)(zn + (size_t)tok * CC))[threadIdx.x];
}

// ---------------- expert FFN layer 1 ----------------
__global__ void __launch_bounds__(256)
ffn1_kernel(const float* __restrict__ eb, const float* __restrict__ W1,
            const float* __restrict__ b1, float* __restrict__ h)
{
    int blk = blockIdx.x;
    int e  = blk >> 6;
    int r0 = (blk & 63) * 4;
    __shared__ float xs[4][CC];
    __shared__ float red[4][4][HIDD];
    int tid = threadIdx.x;
    const float4* src = (const float4*)(eb + ((size_t)e*CAPP + r0) * CC);
    for (int i = tid; i < 4 * (CC/4); i += 256)
        ((float4*)xs)[i] = src[i];
    __syncthreads();
    int kp = tid >> 6;
    int n  = tid & 63;
    float acc[4] = {};
    const float* w = W1 + (size_t)e * CC * HIDD + n;
    #pragma unroll 4
    for (int k = kp; k < CC; k += 4) {
        float wv = w[(size_t)k * HIDD];
        #pragma unroll
        for (int r = 0; r < 4; r++) acc[r] += xs[r][k] * wv;
    }
    #pragma unroll
    for (int r = 0; r < 4; r++) red[kp][r][n] = acc[r];
    __syncthreads();
    {
        int r = tid >> 6, n2 = tid & 63;
        float s = red[0][r][n2] + red[1][r][n2] + red[2][r][n2] + red[3][r][n2]
                + b1[e*HIDD + n2];
        h[((size_t)e*CAPP + r0 + r) * HIDD + n2] = fmaxf(s, 0.f);
    }
}

// ---------------- expert FFN layer 2 ----------------
__global__ void __launch_bounds__(256)
ffn2_kernel(const float* __restrict__ h, const float* __restrict__ W2,
            const float* __restrict__ b2, float* __restrict__ y)
{
    int blk = blockIdx.x;
    int e  = blk >> 6;
    int r0 = (blk & 63) * 4;
    __shared__ float hs[4][HIDD];
    int tid = threadIdx.x;
    hs[tid >> 6][tid & 63] = h[((size_t)e*CAPP + r0 + (tid >> 6)) * HIDD + (tid & 63)];
    __syncthreads();
    int c = tid * 4;
    float4 acc[4];
    #pragma unroll
    for (int r = 0; r < 4; r++) { acc[r].x=0.f; acc[r].y=0.f; acc[r].z=0.f; acc[r].w=0.f; }
    const float* w = W2 + (size_t)e * HIDD * CC + c;
    #pragma unroll 8
    for (int k = 0; k < HIDD; k++) {
        float4 wv = *(const float4*)(w + (size_t)k * CC);
        #pragma unroll
        for (int r = 0; r < 4; r++) {
            float hv = hs[r][k];
            acc[r].x += hv*wv.x; acc[r].y += hv*wv.y;
            acc[r].z += hv*wv.z; acc[r].w += hv*wv.w;
        }
    }
    float4 bb = *(const float4*)(b2 + (size_t)e * CC + c);
    #pragma unroll
    for (int r = 0; r < 4; r++) {
        float4 o;
        o.x = acc[r].x + bb.x; o.y = acc[r].y + bb.y;
        o.z = acc[r].z + bb.z; o.w = acc[r].w + bb.w;
        *(float4*)(y + ((size_t)e*CAPP + r0 + r) * CC + c) = o;
    }
}

// ---------------- final: out = zn + (kept ? y[slot] : zn) ----------------
__global__ void __launch_bounds__(256)
finalize_kernel(const float* __restrict__ zn, const float* __restrict__ y,
                const int* __restrict__ route, const int* __restrict__ pos,
                float* __restrict__ out)
{
    int tok = blockIdx.x, tid = threadIdx.x;
    int p = pos[tok];
    float4 z = ((const float4*)(zn + (size_t)tok * CC))[tid];
    float4 o;
    if (p < CAPP) {
        float4 yv = ((const float4*)(y + ((size_t)route[tok]*CAPP + p) * CC))[tid];
        o.x = z.x + yv.x; o.y = z.y + yv.y; o.z = z.z + yv.z; o.w = z.w + yv.w;
    } else {
        o.x = 2.f*z.x; o.y = 2.f*z.y; o.z = 2.f*z.z; o.w = 2.f*z.w;
    }
    ((float4*)(out + (size_t)tok * CC))[tid] = o;
}

__global__ void fill_ones_kernel(float* __restrict__ p, int n)
{
    int i = blockIdx.x * 256 + threadIdx.x;
    if (i < n) p[i] = 1.0f;
}

// ---------------- launch ----------------
extern "C" void kernel_launch(void* const* d_in, const int* in_sizes, int n_in,
                              void* d_out, int out_size)
{
    const float* qx  = (const float*)d_in[0];
    const float* kx  = (const float*)d_in[1];
    const float* vx  = (const float*)d_in[2];
    const float* WQ  = (const float*)d_in[4];
    const float* bQ  = (const float*)d_in[5];
    const float* WK  = (const float*)d_in[6];
    const float* bK  = (const float*)d_in[7];
    const float* WV  = (const float*)d_in[8];
    const float* bV  = (const float*)d_in[9];
    const float* WO  = (const float*)d_in[10];
    const float* bO  = (const float*)d_in[11];
    const float* ln1w= (const float*)d_in[12];
    const float* ln1b= (const float*)d_in[13];
    const float* Wsw = (const float*)d_in[14];
    const float* bsw = (const float*)d_in[15];
    const float* W1  = (const float*)d_in[16];
    const float* b1  = (const float*)d_in[17];
    const float* W2  = (const float*)d_in[18];
    const float* b2  = (const float*)d_in[19];
    float* out = (float*)d_out;

    float *pQ, *pK, *pV, *pZ, *pzn, *peb, *ph, *py;
    int *proute, *ppos;
    __nv_bfloat16 *px0, *px1, *px2, *pw0, *pw1, *pw2;
    __nv_bfloat16 *pQ0, *pQ1, *pQ2, *pK0, *pK1, *pK2, *pV0, *pV1, *pV2;
    cudaGetSymbolAddress((void**)&pQ,  g_Q);
    cudaGetSymbolAddress((void**)&pK,  g_K);
    cudaGetSymbolAddress((void**)&pV,  g_V);
    cudaGetSymbolAddress((void**)&pZ,  g_Z);
    cudaGetSymbolAddress((void**)&pzn, g_zn);
    cudaGetSymbolAddress((void**)&peb, g_eb);
    cudaGetSymbolAddress((void**)&ph,  g_h);
    cudaGetSymbolAddress((void**)&py,  g_y);
    cudaGetSymbolAddress((void**)&proute, g_route);
    cudaGetSymbolAddress((void**)&ppos,   g_pos);
    cudaGetSymbolAddress((void**)&px0, g_x0);
    cudaGetSymbolAddress((void**)&px1, g_x1);
    cudaGetSymbolAddress((void**)&px2, g_x2);
    cudaGetSymbolAddress((void**)&pw0, g_w0);
    cudaGetSymbolAddress((void**)&pw1, g_w1);
    cudaGetSymbolAddress((void**)&pw2, g_w2);
    cudaGetSymbolAddress((void**)&pQ0, g_q0);
    cudaGetSymbolAddress((void**)&pQ1, g_q1);
    cudaGetSymbolAddress((void**)&pQ2, g_q2);
    cudaGetSymbolAddress((void**)&pK0, g_k0);
    cudaGetSymbolAddress((void**)&pK1, g_k1);
    cudaGetSymbolAddress((void**)&pK2, g_k2);
    cudaGetSymbolAddress((void**)&pV0, g_v0);
    cudaGetSymbolAddress((void**)&pV1, g_v1);
    cudaGetSymbolAddress((void**)&pV2, g_v2);

    cudaFuncSetAttribute(mma_gemm, cudaFuncAttributeMaxDynamicSharedMemorySize,
                         GEMM_SMEM);
    cudaFuncSetAttribute(attn_mma, cudaFuncAttributeMaxDynamicSharedMemorySize,
                         ATTN_SMEM);

    const int NX4 = NTOK * CC / 4;
    const int NW4 = CC * CC / 4;
    dim3 gemmGrid(CC/128, NTOK/128);

    split3_kernel<<<NX4/256, 256>>>(qx, px0, px1, px2, NX4);
    split3_kernel<<<NW4/256, 256>>>(WQ, pw0, pw1, pw2, NW4);
    mma_gemm<<<gemmGrid, 256, GEMM_SMEM>>>(px0, px1, px2, pw0, pw1, pw2, bQ, pQ);
    split3_kernel<<<NX4/256, 256>>>(kx, px0, px1, px2, NX4);
    split3_kernel<<<NW4/256, 256>>>(WK, pw0, pw1, pw2, NW4);
    mma_gemm<<<gemmGrid, 256, GEMM_SMEM>>>(px0, px1, px2, pw0, pw1, pw2, bK, pK);
    split3_kernel<<<NX4/256, 256>>>(vx, px0, px1, px2, NX4);
    split3_kernel<<<NW4/256, 256>>>(WV, pw0, pw1, pw2, NW4);
    mma_gemm<<<gemmGrid, 256, GEMM_SMEM>>>(px0, px1, px2, pw0, pw1, pw2, bV, pV);

    // split projected Q/K/V for tensor-core attention
    split3_kernel<<<NX4/256, 256>>>(pQ, pQ0, pQ1, pQ2, NX4);
    split3_kernel<<<NX4/256, 256>>>(pK, pK0, pK1, pK2, NX4);
    split3_kernel<<<NX4/256, 256>>>(pV, pV0, pV1, pV2, NX4);

    attn_mma<<<dim3(LL/128, BB*HH), 256, ATTN_SMEM>>>(
        pQ0, pQ1, pQ2, pK0, pK1, pK2, pV0, pV1, pV2, pZ);

    split3_kernel<<<NX4/256, 256>>>(pZ, px0, px1, px2, NX4);
    split3_kernel<<<NW4/256, 256>>>(WO, pw0, pw1, pw2, NW4);
    mma_gemm<<<gemmGrid, 256, GEMM_SMEM>>>(px0, px1, px2, pw0, pw1, pw2, bO, pQ);

    add_ln_kernel<<<NTOK, 256>>>(qx, pQ, ln1w, ln1b, pzn);
    router_kernel<<<NTOK, 128>>>(pzn, Wsw, bsw, proute);
    scanpos_kernel<<<EE, 256>>>(proute, ppos);
    gather_kernel<<<NTOK, 256>>>(pzn, proute, ppos, peb);
    ffn1_kernel<<<EE * (CAPP/4), 256>>>(peb, W1, b1, ph);
    ffn2_kernel<<<EE * (CAPP/4), 256>>>(ph, W2, b2, py);
    finalize_kernel<<<NTOK, 256>>>(pzn, py, proute, ppos, out);

    long long os = (long long)out_size;
    if (os >= (long long)(2 * NCE)) {
        cudaMemcpyAsync(out + NCE, kx, NCE * sizeof(float),
                        cudaMemcpyDeviceToDevice, 0);
    }
    if (os >= (long long)(3 * NCE)) {
        cudaMemcpyAsync(out + 2 * NCE, vx, NCE * sizeof(float),
                        cudaMemcpyDeviceToDevice, 0);
    }
    long long rem = os - (long long)(3 * NCE);
    if (rem > 0) {
        fill_ones_kernel<<<(int)((rem + 255) / 256), 256>>>(out + 3 * NCE, (int)rem);
    }
}